// round 11
// baseline (speedup 1.0000x reference)
#include <cuda_runtime.h>
#include <cuda_fp16.h>
#include <math.h>
#include <float.h>
#include <stdint.h>

// ---------------------------------------------------------------------------
// PointEncoder: FF1 -> FF2 -> 4x attention -> concat -> FF_final
// N=8192, D=512, MD=128, OUT_F=1024.
// FP16 tensor cores (fp32 accumulate), ldmatrix fragment loads.
// No-max softmax (scores provably tiny). Flash mainloop software-pipelined:
// PV of tile kt-1 interleaved with QK/exp of tile kt at 16-key granularity.
// ---------------------------------------------------------------------------

#define NROWS 8192
#define DMODEL 512
#define OUTF 1024

// Activations (fp16)
__device__ __half g_h[NROWS * DMODEL];
__device__ __half g_tmp[NROWS * DMODEL];
__device__ __half g_QKV[NROWS * 768];            // Q(128)|K(128)|V(512) per row
__device__ __half g_AV[NROWS * DMODEL];
__device__ __half g_cat[NROWS * 4 * DMODEL];
// Weights, transposed to [N][K], fp16
__device__ __half g_W2t[DMODEL * DMODEL];
__device__ __half g_Wqkvt[768 * DMODEL];
__device__ __half g_WOt[DMODEL * DMODEL];
__device__ __half g_Wft[OUTF * 4 * DMODEL];

__device__ __forceinline__ uint32_t pack2(float x, float y) {
    __half2 h = __floats2half2_rn(x, y);
    return *(uint32_t*)&h;
}

// ---------------------------------------------------------------------------
// Reductions
// ---------------------------------------------------------------------------
__device__ __forceinline__ float warpReduceSum(float v) {
#pragma unroll
    for (int o = 16; o > 0; o >>= 1) v += __shfl_xor_sync(0xffffffff, v, o);
    return v;
}
__device__ float blockReduceSum(float v) {
    __shared__ float sh[32];
    __shared__ float res;
    int lane = threadIdx.x & 31, wid = threadIdx.x >> 5;
    v = warpReduceSum(v);
    if (lane == 0) sh[wid] = v;
    __syncthreads();
    int nw = (blockDim.x + 31) >> 5;
    float t = (threadIdx.x < nw) ? sh[threadIdx.x] : 0.0f;
    if (wid == 0) { t = warpReduceSum(t); if (lane == 0) res = t; }
    __syncthreads();
    return res;
}

// ---------------------------------------------------------------------------
// cp.async + ldmatrix helpers
// ---------------------------------------------------------------------------
__device__ __forceinline__ void cp16h(__half* dst, const __half* src) {
    uint32_t d = (uint32_t)__cvta_generic_to_shared(dst);
    asm volatile("cp.async.cg.shared.global [%0], [%1], 16;\n" :: "r"(d), "l"(src));
}
__device__ __forceinline__ void cp_commit() { asm volatile("cp.async.commit_group;\n"); }
__device__ __forceinline__ void cp_wait1() { asm volatile("cp.async.wait_group 1;\n"); }
__device__ __forceinline__ void cp_wait0() { asm volatile("cp.async.wait_group 0;\n"); }

__device__ __forceinline__ void ldsm4(uint32_t& r0, uint32_t& r1, uint32_t& r2, uint32_t& r3,
                                      uint32_t addr) {
    asm volatile("ldmatrix.sync.aligned.m8n8.x4.shared.b16 {%0,%1,%2,%3}, [%4];"
                 : "=r"(r0), "=r"(r1), "=r"(r2), "=r"(r3) : "r"(addr));
}
__device__ __forceinline__ void ldsm4t(uint32_t& r0, uint32_t& r1, uint32_t& r2, uint32_t& r3,
                                       uint32_t addr) {
    asm volatile("ldmatrix.sync.aligned.m8n8.x4.trans.shared.b16 {%0,%1,%2,%3}, [%4];"
                 : "=r"(r0), "=r"(r1), "=r"(r2), "=r"(r3) : "r"(addr));
}

#define MMA_F16(c, a0, a1, a2, a3, b0, b1)                                   \
    asm volatile(                                                            \
        "mma.sync.aligned.m16n8k16.row.col.f32.f16.f16.f32 "                 \
        "{%0,%1,%2,%3},{%4,%5,%6,%7},{%8,%9},{%0,%1,%2,%3};"                 \
        : "+f"((c)[0]), "+f"((c)[1]), "+f"((c)[2]), "+f"((c)[3])             \
        : "r"(a0), "r"(a1), "r"(a2), "r"(a3), "r"(b0), "r"(b1))

// ---------------------------------------------------------------------------
// FP16 GEMM (NT): C[M,N] = A[M,K] @ Bt[N,K]^T + bias
// 128x128x32 tile, 256 threads (8 warps 2x4), warp 64x32, mma m16n8k16.
// ---------------------------------------------------------------------------
#define HST 40            // smem row stride in halves (32 + 8 pad; 80B = 5x16)
#define HSZ (128 * HST)   // halves per stage

template <typename OutT>
__global__ void __launch_bounds__(256, 2) gemm_f16(
    int M, int N, int K,
    const __half* __restrict__ A, int lda,
    const __half* __restrict__ Bt, int ldb,
    OutT* __restrict__ C, int ldc,
    const float* __restrict__ bias)
{
    __shared__ __half sm[4 * HSZ];   // A0,A1,B0,B1

    const int t    = threadIdx.x;
    const int wid  = t >> 5;
    const int lane = t & 31;
    const int g    = lane >> 2;
    const int t4   = lane & 3;
    const int wm   = wid & 1;
    const int wn   = wid >> 1;
    const int bx   = blockIdx.x;
    const int by   = blockIdx.y;

    const int arow = lane & 15;
    const int acol = (lane >> 4) << 3;
    const int brow = ((lane >> 4) << 3) | (lane & 7);
    const int bcol = ((lane >> 3) & 1) << 3;

    const uint32_t smb = (uint32_t)__cvta_generic_to_shared(sm);

    const __half* Ab = A  + (size_t)by * 128 * lda;
    const __half* Bb = Bt + (size_t)bx * 128 * ldb;

    const int lr = t >> 1;
    const int lc = (t & 1) * 16;

    float acc[4][4][4];
#pragma unroll
    for (int mt = 0; mt < 4; mt++)
#pragma unroll
        for (int nt = 0; nt < 4; nt++)
#pragma unroll
            for (int r = 0; r < 4; r++) acc[mt][nt][r] = 0.0f;

    const int tiles = K / 32;

    auto load_tile = [&](int stage, int k0) {
        __half* as = sm + stage * HSZ;
        __half* bs = sm + (2 + stage) * HSZ;
        cp16h(as + lr * HST + lc,     Ab + (size_t)lr * lda + k0 + lc);
        cp16h(as + lr * HST + lc + 8, Ab + (size_t)lr * lda + k0 + lc + 8);
        cp16h(bs + lr * HST + lc,     Bb + (size_t)lr * ldb + k0 + lc);
        cp16h(bs + lr * HST + lc + 8, Bb + (size_t)lr * ldb + k0 + lc + 8);
        cp_commit();
    };

    load_tile(0, 0);

    for (int tt = 0; tt < tiles; tt++) {
        if (tt + 1 < tiles) {
            load_tile((tt + 1) & 1, (tt + 1) * 32);
            cp_wait1();
        } else {
            cp_wait0();
        }
        __syncthreads();

        const int stage = tt & 1;
        const uint32_t abase = smb + (stage * HSZ) * 2;
        const uint32_t bbase = smb + ((2 + stage) * HSZ) * 2;

#pragma unroll
        for (int ks = 0; ks < 2; ks++) {
            uint32_t a[4][4];
#pragma unroll
            for (int mt = 0; mt < 4; mt++) {
                uint32_t ad = abase + (((wm * 64 + mt * 16 + arow) * HST) + ks * 16 + acol) * 2;
                ldsm4(a[mt][0], a[mt][1], a[mt][2], a[mt][3], ad);
            }
            uint32_t b[4][2];
#pragma unroll
            for (int np = 0; np < 2; np++) {
                uint32_t bd = bbase + (((wn * 32 + np * 16 + brow) * HST) + ks * 16 + bcol) * 2;
                ldsm4(b[2 * np][0], b[2 * np][1], b[2 * np + 1][0], b[2 * np + 1][1], bd);
            }
#pragma unroll
            for (int mt = 0; mt < 4; mt++)
#pragma unroll
                for (int nt = 0; nt < 4; nt++)
                    MMA_F16(acc[mt][nt], a[mt][0], a[mt][1], a[mt][2], a[mt][3],
                            b[nt][0], b[nt][1]);
        }
        __syncthreads();
    }

#pragma unroll
    for (int mt = 0; mt < 4; mt++) {
        const int gr = by * 128 + wm * 64 + mt * 16 + g;
#pragma unroll
        for (int nt = 0; nt < 4; nt++) {
            const int gc = bx * 128 + wn * 32 + nt * 8 + 2 * t4;
            float b0 = bias ? bias[gc] : 0.0f;
            float b1 = bias ? bias[gc + 1] : 0.0f;
            float v0 = acc[mt][nt][0] + b0;
            float v1 = acc[mt][nt][1] + b1;
            float v2 = acc[mt][nt][2] + b0;
            float v3 = acc[mt][nt][3] + b1;
            if (sizeof(OutT) == 2) {
                *(uint32_t*)((__half*)C + (size_t)gr * ldc + gc)       = pack2(v0, v1);
                *(uint32_t*)((__half*)C + (size_t)(gr + 8) * ldc + gc) = pack2(v2, v3);
            } else {
                *(float2*)((float*)C + (size_t)gr * ldc + gc)       = make_float2(v0, v1);
                *(float2*)((float*)C + (size_t)(gr + 8) * ldc + gc) = make_float2(v2, v3);
            }
        }
    }
}

// ---------------------------------------------------------------------------
// Fused flash attention (fp16), no-max softmax, PV pipelined one tile behind:
//   per tile kt, per 16-key group np: QK(np) mma -> PV(kt-1, np) mma
//   (independent, hides QK latency) -> exp(np) -> pa[np] for next tile.
// K double-buffered (2 stages), V triple-buffered (V(kt-1) stays live).
// ---------------------------------------------------------------------------
#define FKT 64
#define FNT (NROWS / FKT)
#define KST 136                       // K smem stride (halves; 272B)
#define VST 264                       // V smem stride (halves; 528B)
#define QSTG 136                      // Q staging stride (halves; 272B)
#define SMK_SZ (FKT * KST)            // 8704 halves per K stage
#define SMV_SZ (FKT * VST)            // 16896 halves per V stage
#define FLASH_SMEM ((2 * SMK_SZ + 3 * SMV_SZ) * 2)   // 136192 bytes

__global__ void __launch_bounds__(256, 1) flash_kernel(
    const __half* __restrict__ QKV, __half* __restrict__ O)
{
    extern __shared__ __half smh[];
    __half* smK = smh;
    __half* smV = smh + 2 * SMK_SZ;   // 3 V stages; Q staged in stages 0-1 first

    const int t    = threadIdx.x;
    const int w    = t >> 5;
    const int lane = t & 31;
    const int g    = lane >> 2;
    const int t4   = lane & 3;
    const int vh   = blockIdx.x;
    const int qb   = blockIdx.y;

    // ldmatrix lane constants
    const int arow = lane & 15;
    const int acol = (lane >> 4) << 3;
    const int brow = ((lane >> 4) << 3) | (lane & 7);
    const int bcol = ((lane >> 3) & 1) << 3;
    const int vkey = bcol | (lane & 7);
    const int vcg  = (lane >> 4) << 3;

    const uint32_t smb    = (uint32_t)__cvta_generic_to_shared(smh);
    const uint32_t kbase0 = smb;
    const uint32_t vbase0 = smb + (2 * SMK_SZ) * 2;

    const __half* Vg = QKV + 256 + vh * 256;

    // ---- prologue: stage Q (in V area), read Q frags ----
#pragma unroll
    for (int i = 0; i < 8; i++) {
        int idx = t + i * 256;
        int r = idx >> 4, c = (idx & 15) * 8;
        cp16h(smV + r * QSTG + c, QKV + (size_t)(qb * 128 + r) * 768 + c);
    }
    cp_commit();
    cp_wait0();
    __syncthreads();

    uint32_t qa[8][4];
#pragma unroll
    for (int ks = 0; ks < 8; ks++) {
        uint32_t ad = vbase0 + (((w * 16 + arow) * QSTG) + ks * 16 + acol) * 2;
        ldsm4(qa[ks][0], qa[ks][1], qa[ks][2], qa[ks][3], ad);
    }
    __syncthreads();   // all warps have Q frags before K0/V0 overwrite staging

    // group 0: K0 -> K stage 0, V0 -> V stage 0
    {
#pragma unroll
        for (int i = 0; i < 4; i++) {
            int idx = t + i * 256;
            int r = idx >> 4, c = (idx & 15) * 8;
            cp16h(smK + r * KST + c, QKV + (size_t)r * 768 + 128 + c);
        }
#pragma unroll
        for (int i = 0; i < 8; i++) {
            int idx = t + i * 256;
            int r = idx >> 5, c = (idx & 31) * 8;
            cp16h(smV + r * VST + c, Vg + (size_t)r * 768 + c);
        }
        cp_commit();
    }

    const float c_exp = 0.12753102150208952f;   // (1/sqrt(128)) * log2(e)

    float l0 = 0.0f, l1 = 0.0f;
    float o[32][4];
#pragma unroll
    for (int nt = 0; nt < 32; nt++)
#pragma unroll
        for (int r = 0; r < 4; r++) o[nt][r] = 0.0f;

    uint32_t pa[4][4];   // P fragments of the PREVIOUS tile (valid for kt >= 1)

    for (int kt = 0; kt < FNT; kt++) {
        cp_wait0();          // group kt (K(kt), V(kt)) landed
        __syncthreads();     // + consumers done with the stages being overwritten

        if (kt + 1 < FNT) {  // prefetch group kt+1: K -> stage (kt+1)&1, V -> stage (kt+1)%3
            __half* kd = smK + ((kt + 1) & 1) * SMK_SZ;
            __half* vd = smV + ((kt + 1) % 3) * SMV_SZ;
#pragma unroll
            for (int i = 0; i < 4; i++) {
                int idx = t + i * 256;
                int r = idx >> 4, c = (idx & 15) * 8;
                cp16h(kd + r * KST + c,
                      QKV + (size_t)((kt + 1) * FKT + r) * 768 + 128 + c);
            }
#pragma unroll
            for (int i = 0; i < 8; i++) {
                int idx = t + i * 256;
                int r = idx >> 5, c = (idx & 31) * 8;
                cp16h(vd + r * VST + c, Vg + (size_t)((kt + 1) * FKT + r) * 768 + c);
            }
            cp_commit();
        }

        const uint32_t kb  = kbase0 + ((kt & 1) * SMK_SZ) * 2;
        const uint32_t vbp = vbase0 + (((kt + 2) % 3) * SMV_SZ) * 2;  // V(kt-1); valid kt>0

#pragma unroll
        for (int np = 0; np < 4; np++) {
            // ---- QK for key group np of tile kt ----
            float s0[4] = {0.f, 0.f, 0.f, 0.f};
            float s1[4] = {0.f, 0.f, 0.f, 0.f};
#pragma unroll
            for (int ks = 0; ks < 8; ks++) {
                uint32_t b0e, b1e, b0o, b1o;
                uint32_t bd = kb + (((np * 16 + brow) * KST) + ks * 16 + bcol) * 2;
                ldsm4(b0e, b1e, b0o, b1o, bd);
                MMA_F16(s0, qa[ks][0], qa[ks][1], qa[ks][2], qa[ks][3], b0e, b1e);
                MMA_F16(s1, qa[ks][0], qa[ks][1], qa[ks][2], qa[ks][3], b0o, b1o);
            }

            // ---- PV for key group np of tile kt-1 (independent of s0/s1) ----
            if (kt > 0) {
#pragma unroll
                for (int np2 = 0; np2 < 16; np2++) {
                    uint32_t b0e, b1e, b0o, b1o;
                    uint32_t vd = vbp + (((np * 16 + vkey) * VST) + np2 * 16 + vcg) * 2;
                    ldsm4t(b0e, b1e, b0o, b1o, vd);
                    MMA_F16(o[2 * np2],     pa[np][0], pa[np][1], pa[np][2], pa[np][3], b0e, b1e);
                    MMA_F16(o[2 * np2 + 1], pa[np][0], pa[np][1], pa[np][2], pa[np][3], b0o, b1o);
                }
            }

            // ---- exp + pack (QK results have drained behind PV) ----
            float e00 = exp2f(s0[0] * c_exp);
            float e01 = exp2f(s0[1] * c_exp);
            float e02 = exp2f(s0[2] * c_exp);
            float e03 = exp2f(s0[3] * c_exp);
            float e10 = exp2f(s1[0] * c_exp);
            float e11 = exp2f(s1[1] * c_exp);
            float e12 = exp2f(s1[2] * c_exp);
            float e13 = exp2f(s1[3] * c_exp);
            l0 += e00 + e01 + e10 + e11;
            l1 += e02 + e03 + e12 + e13;
            pa[np][0] = pack2(e00, e01);
            pa[np][1] = pack2(e02, e03);
            pa[np][2] = pack2(e10, e11);
            pa[np][3] = pack2(e12, e13);
        }
    }

    // ---- drain: PV for the last tile (V stage (FNT-1)%3, untouched since) ----
    {
        const uint32_t vbl = vbase0 + (((FNT - 1) % 3) * SMV_SZ) * 2;
#pragma unroll
        for (int np = 0; np < 4; np++) {
#pragma unroll
            for (int np2 = 0; np2 < 16; np2++) {
                uint32_t b0e, b1e, b0o, b1o;
                uint32_t vd = vbl + (((np * 16 + vkey) * VST) + np2 * 16 + vcg) * 2;
                ldsm4t(b0e, b1e, b0o, b1o, vd);
                MMA_F16(o[2 * np2],     pa[np][0], pa[np][1], pa[np][2], pa[np][3], b0e, b1e);
                MMA_F16(o[2 * np2 + 1], pa[np][0], pa[np][1], pa[np][2], pa[np][3], b0o, b1o);
            }
        }
    }

    // ---- final l reduction over the quad, then normalize + store ----
    l0 += __shfl_xor_sync(0xffffffff, l0, 1);
    l0 += __shfl_xor_sync(0xffffffff, l0, 2);
    l1 += __shfl_xor_sync(0xffffffff, l1, 1);
    l1 += __shfl_xor_sync(0xffffffff, l1, 2);
    const float il0 = 1.0f / l0;
    const float il1 = 1.0f / l1;
    const int r0 = qb * 128 + w * 16 + g;
    const int colb = vh * 256 + 2 * t4;
#pragma unroll
    for (int nt = 0; nt < 32; nt++) {
        int gc = colb + nt * 8;
        *(uint32_t*)(O + (size_t)r0 * DMODEL + gc) =
            pack2(o[nt][0] * il0, o[nt][1] * il0);
        *(uint32_t*)(O + (size_t)(r0 + 8) * DMODEL + gc) =
            pack2(o[nt][2] * il1, o[nt][3] * il1);
    }
}

// ---------------------------------------------------------------------------
// Weight transpose+cvt: float [K][N] -> half [N][K]
// ---------------------------------------------------------------------------
__global__ void tcvt_kernel(const float* __restrict__ in, int ldin,
                            __half* __restrict__ out, int ldout)
{
    __shared__ float sm[32][33];
    const int k0 = blockIdx.x * 32;
    const int n0 = blockIdx.y * 32;
    const int tx = threadIdx.x & 31;
    const int ty = threadIdx.x >> 5;
#pragma unroll
    for (int i = 0; i < 4; i++)
        sm[ty + 8 * i][tx] = in[(size_t)(k0 + ty + 8 * i) * ldin + n0 + tx];
    __syncthreads();
#pragma unroll
    for (int i = 0; i < 4; i++)
        out[(size_t)(n0 + ty + 8 * i) * ldout + k0 + tx] =
            __float2half_rn(sm[tx][ty + 8 * i]);
}

// ---------------------------------------------------------------------------
// FF1: h = fp16(relu(LN(x @ W1 + b1)))
// ---------------------------------------------------------------------------
__global__ void __launch_bounds__(128) ff1_kernel(
    const float* __restrict__ x, const float* __restrict__ W1,
    const float* __restrict__ b1, const float* __restrict__ g1,
    const float* __restrict__ be1, __half* __restrict__ out)
{
    const int row = blockIdx.x;
    const float x0 = x[row * 3 + 0];
    const float x1 = x[row * 3 + 1];
    const float x2 = x[row * 3 + 2];
    const int t = threadIdx.x;

    float v[4];
    float s = 0.0f, s2 = 0.0f;
#pragma unroll
    for (int i = 0; i < 4; i++) {
        int j = i * 128 + t;
        float val = fmaf(x0, W1[j], fmaf(x1, W1[DMODEL + j], fmaf(x2, W1[2 * DMODEL + j], b1[j])));
        v[i] = val;
        s += val;
        s2 = fmaf(val, val, s2);
    }
    s  = blockReduceSum(s);
    s2 = blockReduceSum(s2);
    const float mean = s * (1.0f / DMODEL);
    const float var  = s2 * (1.0f / DMODEL) - mean * mean;
    const float inv  = rsqrtf(var + 1e-5f);
#pragma unroll
    for (int i = 0; i < 4; i++) {
        int j = i * 128 + t;
        float y = fmaf((v[i] - mean) * inv, g1[j], be1[j]);
        out[(size_t)row * DMODEL + j] = __float2half_rn(fmaxf(y, 0.0f));
    }
}

// ---------------------------------------------------------------------------
// LayerNorm + ReLU, in-place. T = __half or float.
// ---------------------------------------------------------------------------
template <typename T>
__global__ void __launch_bounds__(256) ln_relu_kernel(
    T* __restrict__ X, int D, const float* __restrict__ g, const float* __restrict__ be)
{
    const int row = blockIdx.x;
    T* x = X + (size_t)row * D;
    const int t = threadIdx.x;
    const int per = D >> 8;

    float v[4];
    float s = 0.0f, s2 = 0.0f;
    for (int i = 0; i < per; i++) {
        float val = (float)x[i * 256 + t];
        v[i] = val;
        s += val;
        s2 = fmaf(val, val, s2);
    }
    s  = blockReduceSum(s);
    s2 = blockReduceSum(s2);
    const float invD = 1.0f / (float)D;
    const float mean = s * invD;
    const float var  = s2 * invD - mean * mean;
    const float inv  = rsqrtf(var + 1e-5f);
    for (int i = 0; i < per; i++) {
        int j = i * 256 + t;
        float y = fmaxf(fmaf((v[i] - mean) * inv, g[j], be[j]), 0.0f);
        x[j] = (T)y;
    }
}

// ---------------------------------------------------------------------------
// Host side
// ---------------------------------------------------------------------------
template <typename OutT>
static void launch_gemm(int M, int N, int K,
                        const __half* A, int lda, const __half* Bt, int ldb,
                        OutT* C, int ldc, const float* bias)
{
    dim3 grid(N / 128, M / 128);
    gemm_f16<OutT><<<grid, 256>>>(M, N, K, A, lda, Bt, ldb, C, ldc, bias);
}

extern "C" void kernel_launch(void* const* d_in, const int* in_sizes, int n_in,
                              void* d_out, int out_size)
{
    const float* x   = (const float*)d_in[0];
    const float* W1  = (const float*)d_in[1];
    const float* b1  = (const float*)d_in[2];
    const float* g1  = (const float*)d_in[3];
    const float* be1 = (const float*)d_in[4];
    const float* W2  = (const float*)d_in[5];
    const float* b2  = (const float*)d_in[6];
    const float* g2  = (const float*)d_in[7];
    const float* be2 = (const float*)d_in[8];
    const float* WQ  = (const float*)d_in[9];
    const float* WK  = (const float*)d_in[10];
    const float* WV  = (const float*)d_in[11];
    const float* WO  = (const float*)d_in[12];
    const float* Wf  = (const float*)d_in[13];
    const float* bf  = (const float*)d_in[14];
    const float* gf  = (const float*)d_in[15];
    const float* bef = (const float*)d_in[16];
    float* out = (float*)d_out;

    cudaFuncSetAttribute(flash_kernel, cudaFuncAttributeMaxDynamicSharedMemorySize, FLASH_SMEM);

    __half *h, *tmp, *QKV, *AV, *cat, *W2t, *Wqkvt, *WOt, *Wft;
    cudaGetSymbolAddress((void**)&h,     g_h);
    cudaGetSymbolAddress((void**)&tmp,   g_tmp);
    cudaGetSymbolAddress((void**)&QKV,   g_QKV);
    cudaGetSymbolAddress((void**)&AV,    g_AV);
    cudaGetSymbolAddress((void**)&cat,   g_cat);
    cudaGetSymbolAddress((void**)&W2t,   g_W2t);
    cudaGetSymbolAddress((void**)&Wqkvt, g_Wqkvt);
    cudaGetSymbolAddress((void**)&WOt,   g_WOt);
    cudaGetSymbolAddress((void**)&Wft,   g_Wft);

    // ---- weight prep: transpose + fp16 ----
    tcvt_kernel<<<dim3(16, 16), 256>>>(W2, DMODEL, W2t, DMODEL);
    tcvt_kernel<<<dim3(16, 4),  256>>>(WQ, 128, Wqkvt, DMODEL);
    tcvt_kernel<<<dim3(16, 4),  256>>>(WK, 128, Wqkvt + 128 * DMODEL, DMODEL);
    tcvt_kernel<<<dim3(16, 16), 256>>>(WV, DMODEL, Wqkvt + 256 * DMODEL, DMODEL);
    tcvt_kernel<<<dim3(16, 16), 256>>>(WO, DMODEL, WOt, DMODEL);
    tcvt_kernel<<<dim3(64, 32), 256>>>(Wf, OUTF, Wft, 4 * DMODEL);

    // ---- FF1 ----
    ff1_kernel<<<NROWS, 128>>>(x, W1, b1, g1, be1, h);

    // ---- FF2 ----
    launch_gemm<__half>(NROWS, DMODEL, DMODEL, h, DMODEL, W2t, DMODEL, tmp, DMODEL, b2);
    ln_relu_kernel<__half><<<NROWS, 256>>>(tmp, DMODEL, g2, be2);

    const __half* cur = tmp;
    int ld_cur = DMODEL;

    for (int it = 0; it < 4; it++) {
        // QKV projection
        launch_gemm<__half>(NROWS, 768, DMODEL, cur, ld_cur, Wqkvt, DMODEL, QKV, 768, nullptr);

        // flash attention
        flash_kernel<<<dim3(2, 64), 256, FLASH_SMEM>>>(QKV, AV);

        // a_it = AV @ WO
        __half* a_out = cat + it * DMODEL;
        launch_gemm<__half>(NROWS, DMODEL, DMODEL, AV, DMODEL, WOt, DMODEL, a_out, 4 * DMODEL, nullptr);

        cur = a_out;
        ld_cur = 4 * DMODEL;
    }

    // ---- Final FF ----
    launch_gemm<float>(NROWS, OUTF, 4 * DMODEL, cat, 4 * DMODEL, Wft, 4 * DMODEL, out, OUTF, bf);
    ln_relu_kernel<float><<<NROWS, 256>>>(out, OUTF, gf, bef);
}

// round 12
// speedup vs baseline: 1.0285x; 1.0285x over previous
#include <cuda_runtime.h>
#include <cuda_fp16.h>
#include <math.h>
#include <float.h>
#include <stdint.h>

// ---------------------------------------------------------------------------
// PointEncoder: FF1 -> FF2 -> 4x attention -> concat -> FF_final
// N=8192, D=512, MD=128, OUT_F=1024.
// FP16 tensor cores (fp32 accumulate), ldmatrix fragment loads.
// No-max softmax (scores provably tiny). Flash: 128-key tiles, processed as
// two 64-key halves per sync window (R10 per-half structure, half the syncs).
// ---------------------------------------------------------------------------

#define NROWS 8192
#define DMODEL 512
#define OUTF 1024

// Activations (fp16)
__device__ __half g_h[NROWS * DMODEL];
__device__ __half g_tmp[NROWS * DMODEL];
__device__ __half g_QKV[NROWS * 768];            // Q(128)|K(128)|V(512) per row
__device__ __half g_AV[NROWS * DMODEL];
__device__ __half g_cat[NROWS * 4 * DMODEL];
// Weights, transposed to [N][K], fp16
__device__ __half g_W2t[DMODEL * DMODEL];
__device__ __half g_Wqkvt[768 * DMODEL];
__device__ __half g_WOt[DMODEL * DMODEL];
__device__ __half g_Wft[OUTF * 4 * DMODEL];

__device__ __forceinline__ uint32_t pack2(float x, float y) {
    __half2 h = __floats2half2_rn(x, y);
    return *(uint32_t*)&h;
}

// ---------------------------------------------------------------------------
// Reductions
// ---------------------------------------------------------------------------
__device__ __forceinline__ float warpReduceSum(float v) {
#pragma unroll
    for (int o = 16; o > 0; o >>= 1) v += __shfl_xor_sync(0xffffffff, v, o);
    return v;
}
__device__ float blockReduceSum(float v) {
    __shared__ float sh[32];
    __shared__ float res;
    int lane = threadIdx.x & 31, wid = threadIdx.x >> 5;
    v = warpReduceSum(v);
    if (lane == 0) sh[wid] = v;
    __syncthreads();
    int nw = (blockDim.x + 31) >> 5;
    float t = (threadIdx.x < nw) ? sh[threadIdx.x] : 0.0f;
    if (wid == 0) { t = warpReduceSum(t); if (lane == 0) res = t; }
    __syncthreads();
    return res;
}

// ---------------------------------------------------------------------------
// cp.async + ldmatrix helpers
// ---------------------------------------------------------------------------
__device__ __forceinline__ void cp16h(__half* dst, const __half* src) {
    uint32_t d = (uint32_t)__cvta_generic_to_shared(dst);
    asm volatile("cp.async.cg.shared.global [%0], [%1], 16;\n" :: "r"(d), "l"(src));
}
__device__ __forceinline__ void cp_commit() { asm volatile("cp.async.commit_group;\n"); }
__device__ __forceinline__ void cp_wait1() { asm volatile("cp.async.wait_group 1;\n"); }
__device__ __forceinline__ void cp_wait0() { asm volatile("cp.async.wait_group 0;\n"); }

__device__ __forceinline__ void ldsm4(uint32_t& r0, uint32_t& r1, uint32_t& r2, uint32_t& r3,
                                      uint32_t addr) {
    asm volatile("ldmatrix.sync.aligned.m8n8.x4.shared.b16 {%0,%1,%2,%3}, [%4];"
                 : "=r"(r0), "=r"(r1), "=r"(r2), "=r"(r3) : "r"(addr));
}
__device__ __forceinline__ void ldsm4t(uint32_t& r0, uint32_t& r1, uint32_t& r2, uint32_t& r3,
                                       uint32_t addr) {
    asm volatile("ldmatrix.sync.aligned.m8n8.x4.trans.shared.b16 {%0,%1,%2,%3}, [%4];"
                 : "=r"(r0), "=r"(r1), "=r"(r2), "=r"(r3) : "r"(addr));
}

#define MMA_F16(c, a0, a1, a2, a3, b0, b1)                                   \
    asm volatile(                                                            \
        "mma.sync.aligned.m16n8k16.row.col.f32.f16.f16.f32 "                 \
        "{%0,%1,%2,%3},{%4,%5,%6,%7},{%8,%9},{%0,%1,%2,%3};"                 \
        : "+f"((c)[0]), "+f"((c)[1]), "+f"((c)[2]), "+f"((c)[3])             \
        : "r"(a0), "r"(a1), "r"(a2), "r"(a3), "r"(b0), "r"(b1))

// ---------------------------------------------------------------------------
// FP16 GEMM (NT): C[M,N] = A[M,K] @ Bt[N,K]^T + bias
// 128x128x32 tile, 256 threads (8 warps 2x4), warp 64x32, mma m16n8k16.
// ---------------------------------------------------------------------------
#define HST 40            // smem row stride in halves (32 + 8 pad; 80B = 5x16)
#define HSZ (128 * HST)   // halves per stage

template <typename OutT>
__global__ void __launch_bounds__(256, 2) gemm_f16(
    int M, int N, int K,
    const __half* __restrict__ A, int lda,
    const __half* __restrict__ Bt, int ldb,
    OutT* __restrict__ C, int ldc,
    const float* __restrict__ bias)
{
    __shared__ __half sm[4 * HSZ];   // A0,A1,B0,B1

    const int t    = threadIdx.x;
    const int wid  = t >> 5;
    const int lane = t & 31;
    const int g    = lane >> 2;
    const int t4   = lane & 3;
    const int wm   = wid & 1;
    const int wn   = wid >> 1;
    const int bx   = blockIdx.x;
    const int by   = blockIdx.y;

    const int arow = lane & 15;
    const int acol = (lane >> 4) << 3;
    const int brow = ((lane >> 4) << 3) | (lane & 7);
    const int bcol = ((lane >> 3) & 1) << 3;

    const uint32_t smb = (uint32_t)__cvta_generic_to_shared(sm);

    const __half* Ab = A  + (size_t)by * 128 * lda;
    const __half* Bb = Bt + (size_t)bx * 128 * ldb;

    const int lr = t >> 1;
    const int lc = (t & 1) * 16;

    float acc[4][4][4];
#pragma unroll
    for (int mt = 0; mt < 4; mt++)
#pragma unroll
        for (int nt = 0; nt < 4; nt++)
#pragma unroll
            for (int r = 0; r < 4; r++) acc[mt][nt][r] = 0.0f;

    const int tiles = K / 32;

    auto load_tile = [&](int stage, int k0) {
        __half* as = sm + stage * HSZ;
        __half* bs = sm + (2 + stage) * HSZ;
        cp16h(as + lr * HST + lc,     Ab + (size_t)lr * lda + k0 + lc);
        cp16h(as + lr * HST + lc + 8, Ab + (size_t)lr * lda + k0 + lc + 8);
        cp16h(bs + lr * HST + lc,     Bb + (size_t)lr * ldb + k0 + lc);
        cp16h(bs + lr * HST + lc + 8, Bb + (size_t)lr * ldb + k0 + lc + 8);
        cp_commit();
    };

    load_tile(0, 0);

    for (int tt = 0; tt < tiles; tt++) {
        if (tt + 1 < tiles) {
            load_tile((tt + 1) & 1, (tt + 1) * 32);
            cp_wait1();
        } else {
            cp_wait0();
        }
        __syncthreads();

        const int stage = tt & 1;
        const uint32_t abase = smb + (stage * HSZ) * 2;
        const uint32_t bbase = smb + ((2 + stage) * HSZ) * 2;

#pragma unroll
        for (int ks = 0; ks < 2; ks++) {
            uint32_t a[4][4];
#pragma unroll
            for (int mt = 0; mt < 4; mt++) {
                uint32_t ad = abase + (((wm * 64 + mt * 16 + arow) * HST) + ks * 16 + acol) * 2;
                ldsm4(a[mt][0], a[mt][1], a[mt][2], a[mt][3], ad);
            }
            uint32_t b[4][2];
#pragma unroll
            for (int np = 0; np < 2; np++) {
                uint32_t bd = bbase + (((wn * 32 + np * 16 + brow) * HST) + ks * 16 + bcol) * 2;
                ldsm4(b[2 * np][0], b[2 * np][1], b[2 * np + 1][0], b[2 * np + 1][1], bd);
            }
#pragma unroll
            for (int mt = 0; mt < 4; mt++)
#pragma unroll
                for (int nt = 0; nt < 4; nt++)
                    MMA_F16(acc[mt][nt], a[mt][0], a[mt][1], a[mt][2], a[mt][3],
                            b[nt][0], b[nt][1]);
        }
        __syncthreads();
    }

#pragma unroll
    for (int mt = 0; mt < 4; mt++) {
        const int gr = by * 128 + wm * 64 + mt * 16 + g;
#pragma unroll
        for (int nt = 0; nt < 4; nt++) {
            const int gc = bx * 128 + wn * 32 + nt * 8 + 2 * t4;
            float b0 = bias ? bias[gc] : 0.0f;
            float b1 = bias ? bias[gc + 1] : 0.0f;
            float v0 = acc[mt][nt][0] + b0;
            float v1 = acc[mt][nt][1] + b1;
            float v2 = acc[mt][nt][2] + b0;
            float v3 = acc[mt][nt][3] + b1;
            if (sizeof(OutT) == 2) {
                *(uint32_t*)((__half*)C + (size_t)gr * ldc + gc)       = pack2(v0, v1);
                *(uint32_t*)((__half*)C + (size_t)(gr + 8) * ldc + gc) = pack2(v2, v3);
            } else {
                *(float2*)((float*)C + (size_t)gr * ldc + gc)       = make_float2(v0, v1);
                *(float2*)((float*)C + (size_t)(gr + 8) * ldc + gc) = make_float2(v2, v3);
            }
        }
    }
}

// ---------------------------------------------------------------------------
// Fused flash attention (fp16), no-max softmax:
//   O = (sum_k exp(alpha*QK^T) V) / l
// QKV [8192][768] fp16. Grid (2, 64): x = V half, y = Q block. 256 threads.
// Each warp: 16 Q rows, all keys, 256 V cols. Q frags in registers,
// K ldmatrix, V ldmatrix.trans. 128-key tiles double-buffered; each tile
// processed as two 64-key halves (register pressure identical to R10).
// ONE __syncthreads + ONE cp.async wait per 128 keys.
// ---------------------------------------------------------------------------
#define FKT 128
#define FNT (NROWS / FKT)             // 64 tiles
#define KST 136                       // K smem stride (halves; 272B)
#define VST 264                       // V smem stride (halves; 528B)
#define QSTG 136                      // Q staging stride (halves; 272B)
#define SMK_SZ (FKT * KST)            // 17408 halves per K stage
#define SMV_SZ (FKT * VST)            // 33792 halves per V stage
#define FLASH_SMEM ((2 * SMK_SZ + 2 * SMV_SZ) * 2)   // 204800 bytes

__global__ void __launch_bounds__(256, 1) flash_kernel(
    const __half* __restrict__ QKV, __half* __restrict__ O)
{
    extern __shared__ __half smh[];
    __half* smK = smh;
    __half* smV = smh + 2 * SMK_SZ;   // 2 V stages; Q staged here first

    const int t    = threadIdx.x;
    const int w    = t >> 5;
    const int lane = t & 31;
    const int g    = lane >> 2;
    const int t4   = lane & 3;
    const int vh   = blockIdx.x;
    const int qb   = blockIdx.y;

    // ldmatrix lane constants
    const int arow = lane & 15;
    const int acol = (lane >> 4) << 3;
    const int brow = ((lane >> 4) << 3) | (lane & 7);
    const int bcol = ((lane >> 3) & 1) << 3;
    const int vkey = bcol | (lane & 7);
    const int vcg  = (lane >> 4) << 3;

    const uint32_t smb    = (uint32_t)__cvta_generic_to_shared(smh);
    const uint32_t kbase0 = smb;
    const uint32_t vbase0 = smb + (2 * SMK_SZ) * 2;

    const __half* Vg = QKV + 256 + vh * 256;

    // ---- prologue: stage Q (in V area), read Q frags ----
#pragma unroll
    for (int i = 0; i < 8; i++) {
        int idx = t + i * 256;
        int r = idx >> 4, c = (idx & 15) * 8;
        cp16h(smV + r * QSTG + c, QKV + (size_t)(qb * 128 + r) * 768 + c);
    }
    cp_commit();
    cp_wait0();
    __syncthreads();

    uint32_t qa[8][4];
#pragma unroll
    for (int ks = 0; ks < 8; ks++) {
        uint32_t ad = vbase0 + (((w * 16 + arow) * QSTG) + ks * 16 + acol) * 2;
        ldsm4(qa[ks][0], qa[ks][1], qa[ks][2], qa[ks][3], ad);
    }
    __syncthreads();   // all warps have Q frags before K0/V0 overwrite staging

    // group 0: K tile 0 (128 keys) + V tile 0 (128 keys x 256 cols) -> stage 0
    {
#pragma unroll
        for (int i = 0; i < 8; i++) {
            int idx = t + i * 256;
            int r = idx >> 4, c = (idx & 15) * 8;
            cp16h(smK + r * KST + c, QKV + (size_t)r * 768 + 128 + c);
        }
#pragma unroll
        for (int i = 0; i < 16; i++) {
            int idx = t + i * 256;
            int r = idx >> 5, c = (idx & 31) * 8;
            cp16h(smV + r * VST + c, Vg + (size_t)r * 768 + c);
        }
        cp_commit();
    }

    const float c_exp = 0.12753102150208952f;   // (1/sqrt(128)) * log2(e)

    float l0 = 0.0f, l1 = 0.0f;
    float o[32][4];
#pragma unroll
    for (int nt = 0; nt < 32; nt++)
#pragma unroll
        for (int r = 0; r < 4; r++) o[nt][r] = 0.0f;

    for (int kt = 0; kt < FNT; kt++) {
        cp_wait0();          // group kt landed
        __syncthreads();     // + all warps done with the stage being overwritten

        if (kt + 1 < FNT) {  // prefetch group kt+1 into stage (kt+1)&1
            const int st = (kt + 1) & 1;
            __half* kd = smK + st * SMK_SZ;
            __half* vd = smV + st * SMV_SZ;
#pragma unroll
            for (int i = 0; i < 8; i++) {
                int idx = t + i * 256;
                int r = idx >> 4, c = (idx & 15) * 8;
                cp16h(kd + r * KST + c,
                      QKV + (size_t)((kt + 1) * FKT + r) * 768 + 128 + c);
            }
#pragma unroll
            for (int i = 0; i < 16; i++) {
                int idx = t + i * 256;
                int r = idx >> 5, c = (idx & 31) * 8;
                cp16h(vd + r * VST + c, Vg + (size_t)((kt + 1) * FKT + r) * 768 + c);
            }
            cp_commit();
        }

        const uint32_t kb = kbase0 + ((kt & 1) * SMK_SZ) * 2;
        const uint32_t vb = vbase0 + ((kt & 1) * SMV_SZ) * 2;

        // ---- two 64-key halves, R10 structure each ----
#pragma unroll
        for (int hh = 0; hh < 2; hh++) {
            // S = Q @ K^T (16 rows x 64 keys per warp)
            float s[8][4];
#pragma unroll
            for (int nt = 0; nt < 8; nt++)
#pragma unroll
                for (int r = 0; r < 4; r++) s[nt][r] = 0.0f;

#pragma unroll
            for (int ks = 0; ks < 8; ks++) {
#pragma unroll
                for (int np = 0; np < 4; np++) {
                    uint32_t b0e, b1e, b0o, b1o;
                    uint32_t bd = kb + (((hh * 64 + np * 16 + brow) * KST) + ks * 16 + bcol) * 2;
                    ldsm4(b0e, b1e, b0o, b1o, bd);
                    MMA_F16(s[2 * np],     qa[ks][0], qa[ks][1], qa[ks][2], qa[ks][3], b0e, b1e);
                    MMA_F16(s[2 * np + 1], qa[ks][0], qa[ks][1], qa[ks][2], qa[ks][3], b0o, b1o);
                }
            }

            // p = exp(alpha*s); accumulate l; pack to fp16 A-frag
            uint32_t pa[4][4];
#pragma unroll
            for (int j = 0; j < 4; j++) {
                float e00 = exp2f(s[2 * j][0] * c_exp);
                float e01 = exp2f(s[2 * j][1] * c_exp);
                float e02 = exp2f(s[2 * j][2] * c_exp);
                float e03 = exp2f(s[2 * j][3] * c_exp);
                float e10 = exp2f(s[2 * j + 1][0] * c_exp);
                float e11 = exp2f(s[2 * j + 1][1] * c_exp);
                float e12 = exp2f(s[2 * j + 1][2] * c_exp);
                float e13 = exp2f(s[2 * j + 1][3] * c_exp);
                l0 += e00 + e01 + e10 + e11;
                l1 += e02 + e03 + e12 + e13;
                pa[j][0] = pack2(e00, e01);
                pa[j][1] = pack2(e02, e03);
                pa[j][2] = pack2(e10, e11);
                pa[j][3] = pack2(e12, e13);
            }

            // O += P @ V (V fragments via ldmatrix.trans)
#pragma unroll
            for (int j = 0; j < 4; j++) {
#pragma unroll
                for (int np = 0; np < 16; np++) {
                    uint32_t b0e, b1e, b0o, b1o;
                    uint32_t vd = vb + (((hh * 64 + j * 16 + vkey) * VST) + np * 16 + vcg) * 2;
                    ldsm4t(b0e, b1e, b0o, b1o, vd);
                    MMA_F16(o[2 * np],     pa[j][0], pa[j][1], pa[j][2], pa[j][3], b0e, b1e);
                    MMA_F16(o[2 * np + 1], pa[j][0], pa[j][1], pa[j][2], pa[j][3], b0o, b1o);
                }
            }
        }
    }

    // ---- final l reduction over the quad, then normalize + store ----
    l0 += __shfl_xor_sync(0xffffffff, l0, 1);
    l0 += __shfl_xor_sync(0xffffffff, l0, 2);
    l1 += __shfl_xor_sync(0xffffffff, l1, 1);
    l1 += __shfl_xor_sync(0xffffffff, l1, 2);
    const float il0 = 1.0f / l0;
    const float il1 = 1.0f / l1;
    const int r0 = qb * 128 + w * 16 + g;
    const int colb = vh * 256 + 2 * t4;
#pragma unroll
    for (int nt = 0; nt < 32; nt++) {
        int gc = colb + nt * 8;
        *(uint32_t*)(O + (size_t)r0 * DMODEL + gc) =
            pack2(o[nt][0] * il0, o[nt][1] * il0);
        *(uint32_t*)(O + (size_t)(r0 + 8) * DMODEL + gc) =
            pack2(o[nt][2] * il1, o[nt][3] * il1);
    }
}

// ---------------------------------------------------------------------------
// Weight transpose+cvt: float [K][N] -> half [N][K]
// ---------------------------------------------------------------------------
__global__ void tcvt_kernel(const float* __restrict__ in, int ldin,
                            __half* __restrict__ out, int ldout)
{
    __shared__ float sm[32][33];
    const int k0 = blockIdx.x * 32;
    const int n0 = blockIdx.y * 32;
    const int tx = threadIdx.x & 31;
    const int ty = threadIdx.x >> 5;
#pragma unroll
    for (int i = 0; i < 4; i++)
        sm[ty + 8 * i][tx] = in[(size_t)(k0 + ty + 8 * i) * ldin + n0 + tx];
    __syncthreads();
#pragma unroll
    for (int i = 0; i < 4; i++)
        out[(size_t)(n0 + ty + 8 * i) * ldout + k0 + tx] =
            __float2half_rn(sm[tx][ty + 8 * i]);
}

// ---------------------------------------------------------------------------
// FF1: h = fp16(relu(LN(x @ W1 + b1)))
// ---------------------------------------------------------------------------
__global__ void __launch_bounds__(128) ff1_kernel(
    const float* __restrict__ x, const float* __restrict__ W1,
    const float* __restrict__ b1, const float* __restrict__ g1,
    const float* __restrict__ be1, __half* __restrict__ out)
{
    const int row = blockIdx.x;
    const float x0 = x[row * 3 + 0];
    const float x1 = x[row * 3 + 1];
    const float x2 = x[row * 3 + 2];
    const int t = threadIdx.x;

    float v[4];
    float s = 0.0f, s2 = 0.0f;
#pragma unroll
    for (int i = 0; i < 4; i++) {
        int j = i * 128 + t;
        float val = fmaf(x0, W1[j], fmaf(x1, W1[DMODEL + j], fmaf(x2, W1[2 * DMODEL + j], b1[j])));
        v[i] = val;
        s += val;
        s2 = fmaf(val, val, s2);
    }
    s  = blockReduceSum(s);
    s2 = blockReduceSum(s2);
    const float mean = s * (1.0f / DMODEL);
    const float var  = s2 * (1.0f / DMODEL) - mean * mean;
    const float inv  = rsqrtf(var + 1e-5f);
#pragma unroll
    for (int i = 0; i < 4; i++) {
        int j = i * 128 + t;
        float y = fmaf((v[i] - mean) * inv, g1[j], be1[j]);
        out[(size_t)row * DMODEL + j] = __float2half_rn(fmaxf(y, 0.0f));
    }
}

// ---------------------------------------------------------------------------
// LayerNorm + ReLU, in-place. T = __half or float.
// ---------------------------------------------------------------------------
template <typename T>
__global__ void __launch_bounds__(256) ln_relu_kernel(
    T* __restrict__ X, int D, const float* __restrict__ g, const float* __restrict__ be)
{
    const int row = blockIdx.x;
    T* x = X + (size_t)row * D;
    const int t = threadIdx.x;
    const int per = D >> 8;

    float v[4];
    float s = 0.0f, s2 = 0.0f;
    for (int i = 0; i < per; i++) {
        float val = (float)x[i * 256 + t];
        v[i] = val;
        s += val;
        s2 = fmaf(val, val, s2);
    }
    s  = blockReduceSum(s);
    s2 = blockReduceSum(s2);
    const float invD = 1.0f / (float)D;
    const float mean = s * invD;
    const float var  = s2 * invD - mean * mean;
    const float inv  = rsqrtf(var + 1e-5f);
    for (int i = 0; i < per; i++) {
        int j = i * 256 + t;
        float y = fmaxf(fmaf((v[i] - mean) * inv, g[j], be[j]), 0.0f);
        x[j] = (T)y;
    }
}

// ---------------------------------------------------------------------------
// Host side
// ---------------------------------------------------------------------------
template <typename OutT>
static void launch_gemm(int M, int N, int K,
                        const __half* A, int lda, const __half* Bt, int ldb,
                        OutT* C, int ldc, const float* bias)
{
    dim3 grid(N / 128, M / 128);
    gemm_f16<OutT><<<grid, 256>>>(M, N, K, A, lda, Bt, ldb, C, ldc, bias);
}

extern "C" void kernel_launch(void* const* d_in, const int* in_sizes, int n_in,
                              void* d_out, int out_size)
{
    const float* x   = (const float*)d_in[0];
    const float* W1  = (const float*)d_in[1];
    const float* b1  = (const float*)d_in[2];
    const float* g1  = (const float*)d_in[3];
    const float* be1 = (const float*)d_in[4];
    const float* W2  = (const float*)d_in[5];
    const float* b2  = (const float*)d_in[6];
    const float* g2  = (const float*)d_in[7];
    const float* be2 = (const float*)d_in[8];
    const float* WQ  = (const float*)d_in[9];
    const float* WK  = (const float*)d_in[10];
    const float* WV  = (const float*)d_in[11];
    const float* WO  = (const float*)d_in[12];
    const float* Wf  = (const float*)d_in[13];
    const float* bf  = (const float*)d_in[14];
    const float* gf  = (const float*)d_in[15];
    const float* bef = (const float*)d_in[16];
    float* out = (float*)d_out;

    cudaFuncSetAttribute(flash_kernel, cudaFuncAttributeMaxDynamicSharedMemorySize, FLASH_SMEM);

    __half *h, *tmp, *QKV, *AV, *cat, *W2t, *Wqkvt, *WOt, *Wft;
    cudaGetSymbolAddress((void**)&h,     g_h);
    cudaGetSymbolAddress((void**)&tmp,   g_tmp);
    cudaGetSymbolAddress((void**)&QKV,   g_QKV);
    cudaGetSymbolAddress((void**)&AV,    g_AV);
    cudaGetSymbolAddress((void**)&cat,   g_cat);
    cudaGetSymbolAddress((void**)&W2t,   g_W2t);
    cudaGetSymbolAddress((void**)&Wqkvt, g_Wqkvt);
    cudaGetSymbolAddress((void**)&WOt,   g_WOt);
    cudaGetSymbolAddress((void**)&Wft,   g_Wft);

    // ---- weight prep: transpose + fp16 ----
    tcvt_kernel<<<dim3(16, 16), 256>>>(W2, DMODEL, W2t, DMODEL);
    tcvt_kernel<<<dim3(16, 4),  256>>>(WQ, 128, Wqkvt, DMODEL);
    tcvt_kernel<<<dim3(16, 4),  256>>>(WK, 128, Wqkvt + 128 * DMODEL, DMODEL);
    tcvt_kernel<<<dim3(16, 16), 256>>>(WV, DMODEL, Wqkvt + 256 * DMODEL, DMODEL);
    tcvt_kernel<<<dim3(16, 16), 256>>>(WO, DMODEL, WOt, DMODEL);
    tcvt_kernel<<<dim3(64, 32), 256>>>(Wf, OUTF, Wft, 4 * DMODEL);

    // ---- FF1 ----
    ff1_kernel<<<NROWS, 128>>>(x, W1, b1, g1, be1, h);

    // ---- FF2 ----
    launch_gemm<__half>(NROWS, DMODEL, DMODEL, h, DMODEL, W2t, DMODEL, tmp, DMODEL, b2);
    ln_relu_kernel<__half><<<NROWS, 256>>>(tmp, DMODEL, g2, be2);

    const __half* cur = tmp;
    int ld_cur = DMODEL;

    for (int it = 0; it < 4; it++) {
        // QKV projection
        launch_gemm<__half>(NROWS, 768, DMODEL, cur, ld_cur, Wqkvt, DMODEL, QKV, 768, nullptr);

        // flash attention
        flash_kernel<<<dim3(2, 64), 256, FLASH_SMEM>>>(QKV, AV);

        // a_it = AV @ WO
        __half* a_out = cat + it * DMODEL;
        launch_gemm<__half>(NROWS, DMODEL, DMODEL, AV, DMODEL, WOt, DMODEL, a_out, 4 * DMODEL, nullptr);

        cur = a_out;
        ld_cur = 4 * DMODEL;
    }

    // ---- Final FF ----
    launch_gemm<float>(NROWS, OUTF, 4 * DMODEL, cat, 4 * DMODEL, Wft, 4 * DMODEL, out, OUTF, bf);
    ln_relu_kernel<float><<<NROWS, 256>>>(out, OUTF, gf, bef);
}

// round 13
// speedup vs baseline: 1.0510x; 1.0219x over previous
#include <cuda_runtime.h>
#include <cuda_fp16.h>
#include <math.h>
#include <float.h>
#include <stdint.h>

// ---------------------------------------------------------------------------
// PointEncoder: FF1 -> FF2 -> 4x attention -> concat -> FF_final
// N=8192, D=512, MD=128, OUT_F=1024.
// FP16 tensor cores (fp32 accumulate), ldmatrix fragment loads.
// No-max softmax. Flash = R10 shape (known best).
// NEW: QKV_{i+1} = AV_i @ (WO*Wqkv) fused -> one split-output GEMM per iter.
// ---------------------------------------------------------------------------

#define NROWS 8192
#define DMODEL 512
#define OUTF 1024

// Activations (fp16)
__device__ __half g_h[NROWS * DMODEL];
__device__ __half g_tmp[NROWS * DMODEL];
__device__ __half g_QKV[NROWS * 768];            // Q(128)|K(128)|V(512) per row
__device__ __half g_AV[NROWS * DMODEL];
__device__ __half g_cat[NROWS * 4 * DMODEL];
// Weights (fp16)
__device__ __half g_W2t[DMODEL * DMODEL];        // [N][K]
__device__ __half g_Wqkvt[768 * DMODEL];         // [N][K]
__device__ __half g_WOh[DMODEL * DMODEL];        // WO plain convert [512][512]
__device__ __half g_Wcombt[1280 * DMODEL];       // rows 0-511: WO^T; 512-1279: (WO*Wqkv)^T
__device__ __half g_Wft[OUTF * 4 * DMODEL];

__device__ __forceinline__ uint32_t pack2(float x, float y) {
    __half2 h = __floats2half2_rn(x, y);
    return *(uint32_t*)&h;
}

// ---------------------------------------------------------------------------
// Reductions
// ---------------------------------------------------------------------------
__device__ __forceinline__ float warpReduceSum(float v) {
#pragma unroll
    for (int o = 16; o > 0; o >>= 1) v += __shfl_xor_sync(0xffffffff, v, o);
    return v;
}
__device__ float blockReduceSum(float v) {
    __shared__ float sh[32];
    __shared__ float res;
    int lane = threadIdx.x & 31, wid = threadIdx.x >> 5;
    v = warpReduceSum(v);
    if (lane == 0) sh[wid] = v;
    __syncthreads();
    int nw = (blockDim.x + 31) >> 5;
    float t = (threadIdx.x < nw) ? sh[threadIdx.x] : 0.0f;
    if (wid == 0) { t = warpReduceSum(t); if (lane == 0) res = t; }
    __syncthreads();
    return res;
}

// ---------------------------------------------------------------------------
// cp.async + ldmatrix helpers
// ---------------------------------------------------------------------------
__device__ __forceinline__ void cp16h(__half* dst, const __half* src) {
    uint32_t d = (uint32_t)__cvta_generic_to_shared(dst);
    asm volatile("cp.async.cg.shared.global [%0], [%1], 16;\n" :: "r"(d), "l"(src));
}
__device__ __forceinline__ void cp_commit() { asm volatile("cp.async.commit_group;\n"); }
__device__ __forceinline__ void cp_wait1() { asm volatile("cp.async.wait_group 1;\n"); }
__device__ __forceinline__ void cp_wait0() { asm volatile("cp.async.wait_group 0;\n"); }

__device__ __forceinline__ void ldsm4(uint32_t& r0, uint32_t& r1, uint32_t& r2, uint32_t& r3,
                                      uint32_t addr) {
    asm volatile("ldmatrix.sync.aligned.m8n8.x4.shared.b16 {%0,%1,%2,%3}, [%4];"
                 : "=r"(r0), "=r"(r1), "=r"(r2), "=r"(r3) : "r"(addr));
}
__device__ __forceinline__ void ldsm4t(uint32_t& r0, uint32_t& r1, uint32_t& r2, uint32_t& r3,
                                       uint32_t addr) {
    asm volatile("ldmatrix.sync.aligned.m8n8.x4.trans.shared.b16 {%0,%1,%2,%3}, [%4];"
                 : "=r"(r0), "=r"(r1), "=r"(r2), "=r"(r3) : "r"(addr));
}

#define MMA_F16(c, a0, a1, a2, a3, b0, b1)                                   \
    asm volatile(                                                            \
        "mma.sync.aligned.m16n8k16.row.col.f32.f16.f16.f32 "                 \
        "{%0,%1,%2,%3},{%4,%5,%6,%7},{%8,%9},{%0,%1,%2,%3};"                 \
        : "+f"((c)[0]), "+f"((c)[1]), "+f"((c)[2]), "+f"((c)[3])             \
        : "r"(a0), "r"(a1), "r"(a2), "r"(a3), "r"(b0), "r"(b1))

// ---------------------------------------------------------------------------
// FP16 GEMM (NT): C[M,N] = A[M,K] @ Bt[N,K]^T + bias
// 128x128x32 tile, 256 threads (8 warps 2x4), warp 64x32, mma m16n8k16.
// Split output: block tiles with bx*128 >= nsplit write to C2 (ldc2),
// with column index rebased by nsplit. (Tiles never straddle nsplit.)
// ---------------------------------------------------------------------------
#define HST 40            // smem row stride in halves (32 + 8 pad; 80B = 5x16)
#define HSZ (128 * HST)   // halves per stage

template <typename OutT>
__global__ void __launch_bounds__(256, 2) gemm_f16(
    int M, int N, int K,
    const __half* __restrict__ A, int lda,
    const __half* __restrict__ Bt, int ldb,
    OutT* __restrict__ C, int ldc,
    const float* __restrict__ bias,
    OutT* __restrict__ C2, int ldc2, int nsplit)
{
    __shared__ __half sm[4 * HSZ];   // A0,A1,B0,B1

    const int t    = threadIdx.x;
    const int wid  = t >> 5;
    const int lane = t & 31;
    const int g    = lane >> 2;
    const int t4   = lane & 3;
    const int wm   = wid & 1;
    const int wn   = wid >> 1;
    const int bx   = blockIdx.x;
    const int by   = blockIdx.y;

    const int arow = lane & 15;
    const int acol = (lane >> 4) << 3;
    const int brow = ((lane >> 4) << 3) | (lane & 7);
    const int bcol = ((lane >> 3) & 1) << 3;

    const uint32_t smb = (uint32_t)__cvta_generic_to_shared(sm);

    const __half* Ab = A  + (size_t)by * 128 * lda;
    const __half* Bb = Bt + (size_t)bx * 128 * ldb;

    const int lr = t >> 1;
    const int lc = (t & 1) * 16;

    float acc[4][4][4];
#pragma unroll
    for (int mt = 0; mt < 4; mt++)
#pragma unroll
        for (int nt = 0; nt < 4; nt++)
#pragma unroll
            for (int r = 0; r < 4; r++) acc[mt][nt][r] = 0.0f;

    const int tiles = K / 32;

    auto load_tile = [&](int stage, int k0) {
        __half* as = sm + stage * HSZ;
        __half* bs = sm + (2 + stage) * HSZ;
        cp16h(as + lr * HST + lc,     Ab + (size_t)lr * lda + k0 + lc);
        cp16h(as + lr * HST + lc + 8, Ab + (size_t)lr * lda + k0 + lc + 8);
        cp16h(bs + lr * HST + lc,     Bb + (size_t)lr * ldb + k0 + lc);
        cp16h(bs + lr * HST + lc + 8, Bb + (size_t)lr * ldb + k0 + lc + 8);
        cp_commit();
    };

    load_tile(0, 0);

    for (int tt = 0; tt < tiles; tt++) {
        if (tt + 1 < tiles) {
            load_tile((tt + 1) & 1, (tt + 1) * 32);
            cp_wait1();
        } else {
            cp_wait0();
        }
        __syncthreads();

        const int stage = tt & 1;
        const uint32_t abase = smb + (stage * HSZ) * 2;
        const uint32_t bbase = smb + ((2 + stage) * HSZ) * 2;

#pragma unroll
        for (int ks = 0; ks < 2; ks++) {
            uint32_t a[4][4];
#pragma unroll
            for (int mt = 0; mt < 4; mt++) {
                uint32_t ad = abase + (((wm * 64 + mt * 16 + arow) * HST) + ks * 16 + acol) * 2;
                ldsm4(a[mt][0], a[mt][1], a[mt][2], a[mt][3], ad);
            }
            uint32_t b[4][2];
#pragma unroll
            for (int np = 0; np < 2; np++) {
                uint32_t bd = bbase + (((wn * 32 + np * 16 + brow) * HST) + ks * 16 + bcol) * 2;
                ldsm4(b[2 * np][0], b[2 * np][1], b[2 * np + 1][0], b[2 * np + 1][1], bd);
            }
#pragma unroll
            for (int mt = 0; mt < 4; mt++)
#pragma unroll
                for (int nt = 0; nt < 4; nt++)
                    MMA_F16(acc[mt][nt], a[mt][0], a[mt][1], a[mt][2], a[mt][3],
                            b[nt][0], b[nt][1]);
        }
        __syncthreads();
    }

    // ---- epilogue with per-CTA output select ----
    OutT* Cw;
    int ldw, csub;
    if (bx * 128 < nsplit) { Cw = C;  ldw = ldc;  csub = 0; }
    else                   { Cw = C2; ldw = ldc2; csub = nsplit; }

#pragma unroll
    for (int mt = 0; mt < 4; mt++) {
        const int gr = by * 128 + wm * 64 + mt * 16 + g;
#pragma unroll
        for (int nt = 0; nt < 4; nt++) {
            const int gc = bx * 128 + wn * 32 + nt * 8 + 2 * t4;
            float b0 = bias ? bias[gc] : 0.0f;
            float b1 = bias ? bias[gc + 1] : 0.0f;
            float v0 = acc[mt][nt][0] + b0;
            float v1 = acc[mt][nt][1] + b1;
            float v2 = acc[mt][nt][2] + b0;
            float v3 = acc[mt][nt][3] + b1;
            const int gw = gc - csub;
            if (sizeof(OutT) == 2) {
                *(uint32_t*)((__half*)Cw + (size_t)gr * ldw + gw)       = pack2(v0, v1);
                *(uint32_t*)((__half*)Cw + (size_t)(gr + 8) * ldw + gw) = pack2(v2, v3);
            } else {
                *(float2*)((float*)Cw + (size_t)gr * ldw + gw)       = make_float2(v0, v1);
                *(float2*)((float*)Cw + (size_t)(gr + 8) * ldw + gw) = make_float2(v2, v3);
            }
        }
    }
}

// ---------------------------------------------------------------------------
// Fused flash attention (fp16), no-max softmax (R10 structure, unchanged):
//   O = (sum_k exp(alpha*QK^T) V) / l
// ---------------------------------------------------------------------------
#define FKT 64
#define FNT (NROWS / FKT)
#define KST 136
#define VST 264
#define QSTG 136
#define SMK_SZ (FKT * KST)
#define SMV_SZ (FKT * VST)
#define FLASH_SMEM ((2 * SMK_SZ + 2 * SMV_SZ) * 2)   // 102400 bytes

__global__ void __launch_bounds__(256, 1) flash_kernel(
    const __half* __restrict__ QKV, __half* __restrict__ O)
{
    extern __shared__ __half smh[];
    __half* smK = smh;
    __half* smV = smh + 2 * SMK_SZ;

    const int t    = threadIdx.x;
    const int w    = t >> 5;
    const int lane = t & 31;
    const int g    = lane >> 2;
    const int t4   = lane & 3;
    const int vh   = blockIdx.x;
    const int qb   = blockIdx.y;

    const int arow = lane & 15;
    const int acol = (lane >> 4) << 3;
    const int brow = ((lane >> 4) << 3) | (lane & 7);
    const int bcol = ((lane >> 3) & 1) << 3;
    const int vkey = bcol | (lane & 7);
    const int vcg  = (lane >> 4) << 3;

    const uint32_t smb    = (uint32_t)__cvta_generic_to_shared(smh);
    const uint32_t kbase0 = smb;
    const uint32_t vbase0 = smb + (2 * SMK_SZ) * 2;

    const __half* Vg = QKV + 256 + vh * 256;

#pragma unroll
    for (int i = 0; i < 8; i++) {
        int idx = t + i * 256;
        int r = idx >> 4, c = (idx & 15) * 8;
        cp16h(smV + r * QSTG + c, QKV + (size_t)(qb * 128 + r) * 768 + c);
    }
    cp_commit();
    cp_wait0();
    __syncthreads();

    uint32_t qa[8][4];
#pragma unroll
    for (int ks = 0; ks < 8; ks++) {
        uint32_t ad = vbase0 + (((w * 16 + arow) * QSTG) + ks * 16 + acol) * 2;
        ldsm4(qa[ks][0], qa[ks][1], qa[ks][2], qa[ks][3], ad);
    }
    __syncthreads();

    {
#pragma unroll
        for (int i = 0; i < 4; i++) {
            int idx = t + i * 256;
            int r = idx >> 4, c = (idx & 15) * 8;
            cp16h(smK + r * KST + c, QKV + (size_t)r * 768 + 128 + c);
        }
#pragma unroll
        for (int i = 0; i < 8; i++) {
            int idx = t + i * 256;
            int r = idx >> 5, c = (idx & 31) * 8;
            cp16h(smV + r * VST + c, Vg + (size_t)r * 768 + c);
        }
        cp_commit();
    }

    const float c_exp = 0.12753102150208952f;   // (1/sqrt(128)) * log2(e)

    float l0 = 0.0f, l1 = 0.0f;
    float o[32][4];
#pragma unroll
    for (int nt = 0; nt < 32; nt++)
#pragma unroll
        for (int r = 0; r < 4; r++) o[nt][r] = 0.0f;

    for (int kt = 0; kt < FNT; kt++) {
        cp_wait0();
        __syncthreads();

        if (kt + 1 < FNT) {
            const int st = (kt + 1) & 1;
            __half* kd = smK + st * SMK_SZ;
            __half* vd = smV + st * SMV_SZ;
#pragma unroll
            for (int i = 0; i < 4; i++) {
                int idx = t + i * 256;
                int r = idx >> 4, c = (idx & 15) * 8;
                cp16h(kd + r * KST + c,
                      QKV + (size_t)((kt + 1) * FKT + r) * 768 + 128 + c);
            }
#pragma unroll
            for (int i = 0; i < 8; i++) {
                int idx = t + i * 256;
                int r = idx >> 5, c = (idx & 31) * 8;
                cp16h(vd + r * VST + c, Vg + (size_t)((kt + 1) * FKT + r) * 768 + c);
            }
            cp_commit();
        }

        float s[8][4];
#pragma unroll
        for (int nt = 0; nt < 8; nt++)
#pragma unroll
            for (int r = 0; r < 4; r++) s[nt][r] = 0.0f;

        const uint32_t kb = kbase0 + ((kt & 1) * SMK_SZ) * 2;
#pragma unroll
        for (int ks = 0; ks < 8; ks++) {
#pragma unroll
            for (int np = 0; np < 4; np++) {
                uint32_t b0e, b1e, b0o, b1o;
                uint32_t bd = kb + (((np * 16 + brow) * KST) + ks * 16 + bcol) * 2;
                ldsm4(b0e, b1e, b0o, b1o, bd);
                MMA_F16(s[2 * np],     qa[ks][0], qa[ks][1], qa[ks][2], qa[ks][3], b0e, b1e);
                MMA_F16(s[2 * np + 1], qa[ks][0], qa[ks][1], qa[ks][2], qa[ks][3], b0o, b1o);
            }
        }

        uint32_t pa[4][4];
#pragma unroll
        for (int j = 0; j < 4; j++) {
            float e00 = exp2f(s[2 * j][0] * c_exp);
            float e01 = exp2f(s[2 * j][1] * c_exp);
            float e02 = exp2f(s[2 * j][2] * c_exp);
            float e03 = exp2f(s[2 * j][3] * c_exp);
            float e10 = exp2f(s[2 * j + 1][0] * c_exp);
            float e11 = exp2f(s[2 * j + 1][1] * c_exp);
            float e12 = exp2f(s[2 * j + 1][2] * c_exp);
            float e13 = exp2f(s[2 * j + 1][3] * c_exp);
            l0 += e00 + e01 + e10 + e11;
            l1 += e02 + e03 + e12 + e13;
            pa[j][0] = pack2(e00, e01);
            pa[j][1] = pack2(e02, e03);
            pa[j][2] = pack2(e10, e11);
            pa[j][3] = pack2(e12, e13);
        }

        const uint32_t vb = vbase0 + ((kt & 1) * SMV_SZ) * 2;
#pragma unroll
        for (int j = 0; j < 4; j++) {
#pragma unroll
            for (int np = 0; np < 16; np++) {
                uint32_t b0e, b1e, b0o, b1o;
                uint32_t vd = vb + (((j * 16 + vkey) * VST) + np * 16 + vcg) * 2;
                ldsm4t(b0e, b1e, b0o, b1o, vd);
                MMA_F16(o[2 * np],     pa[j][0], pa[j][1], pa[j][2], pa[j][3], b0e, b1e);
                MMA_F16(o[2 * np + 1], pa[j][0], pa[j][1], pa[j][2], pa[j][3], b0o, b1o);
            }
        }
    }

    l0 += __shfl_xor_sync(0xffffffff, l0, 1);
    l0 += __shfl_xor_sync(0xffffffff, l0, 2);
    l1 += __shfl_xor_sync(0xffffffff, l1, 1);
    l1 += __shfl_xor_sync(0xffffffff, l1, 2);
    const float il0 = 1.0f / l0;
    const float il1 = 1.0f / l1;
    const int r0 = qb * 128 + w * 16 + g;
    const int colb = vh * 256 + 2 * t4;
#pragma unroll
    for (int nt = 0; nt < 32; nt++) {
        int gc = colb + nt * 8;
        *(uint32_t*)(O + (size_t)r0 * DMODEL + gc) =
            pack2(o[nt][0] * il0, o[nt][1] * il0);
        *(uint32_t*)(O + (size_t)(r0 + 8) * DMODEL + gc) =
            pack2(o[nt][2] * il1, o[nt][3] * il1);
    }
}

// ---------------------------------------------------------------------------
// Weight transpose+cvt: float [K][N] -> half [N][K]
// ---------------------------------------------------------------------------
__global__ void tcvt_kernel(const float* __restrict__ in, int ldin,
                            __half* __restrict__ out, int ldout)
{
    __shared__ float sm[32][33];
    const int k0 = blockIdx.x * 32;
    const int n0 = blockIdx.y * 32;
    const int tx = threadIdx.x & 31;
    const int ty = threadIdx.x >> 5;
#pragma unroll
    for (int i = 0; i < 4; i++)
        sm[ty + 8 * i][tx] = in[(size_t)(k0 + ty + 8 * i) * ldin + n0 + tx];
    __syncthreads();
#pragma unroll
    for (int i = 0; i < 4; i++)
        out[(size_t)(n0 + ty + 8 * i) * ldout + k0 + tx] =
            __float2half_rn(sm[tx][ty + 8 * i]);
}

// Plain float -> half convert (no transpose)
__global__ void cvt_kernel(const float* __restrict__ in, __half* __restrict__ out, int n)
{
    int i = blockIdx.x * blockDim.x + threadIdx.x;
    if (i < n) out[i] = __float2half_rn(in[i]);
}

// ---------------------------------------------------------------------------
// FF1: h = fp16(relu(LN(x @ W1 + b1)))
// ---------------------------------------------------------------------------
__global__ void __launch_bounds__(128) ff1_kernel(
    const float* __restrict__ x, const float* __restrict__ W1,
    const float* __restrict__ b1, const float* __restrict__ g1,
    const float* __restrict__ be1, __half* __restrict__ out)
{
    const int row = blockIdx.x;
    const float x0 = x[row * 3 + 0];
    const float x1 = x[row * 3 + 1];
    const float x2 = x[row * 3 + 2];
    const int t = threadIdx.x;

    float v[4];
    float s = 0.0f, s2 = 0.0f;
#pragma unroll
    for (int i = 0; i < 4; i++) {
        int j = i * 128 + t;
        float val = fmaf(x0, W1[j], fmaf(x1, W1[DMODEL + j], fmaf(x2, W1[2 * DMODEL + j], b1[j])));
        v[i] = val;
        s += val;
        s2 = fmaf(val, val, s2);
    }
    s  = blockReduceSum(s);
    s2 = blockReduceSum(s2);
    const float mean = s * (1.0f / DMODEL);
    const float var  = s2 * (1.0f / DMODEL) - mean * mean;
    const float inv  = rsqrtf(var + 1e-5f);
#pragma unroll
    for (int i = 0; i < 4; i++) {
        int j = i * 128 + t;
        float y = fmaf((v[i] - mean) * inv, g1[j], be1[j]);
        out[(size_t)row * DMODEL + j] = __float2half_rn(fmaxf(y, 0.0f));
    }
}

// ---------------------------------------------------------------------------
// LayerNorm + ReLU, in-place. T = __half or float.
// ---------------------------------------------------------------------------
template <typename T>
__global__ void __launch_bounds__(256) ln_relu_kernel(
    T* __restrict__ X, int D, const float* __restrict__ g, const float* __restrict__ be)
{
    const int row = blockIdx.x;
    T* x = X + (size_t)row * D;
    const int t = threadIdx.x;
    const int per = D >> 8;

    float v[4];
    float s = 0.0f, s2 = 0.0f;
    for (int i = 0; i < per; i++) {
        float val = (float)x[i * 256 + t];
        v[i] = val;
        s += val;
        s2 = fmaf(val, val, s2);
    }
    s  = blockReduceSum(s);
    s2 = blockReduceSum(s2);
    const float invD = 1.0f / (float)D;
    const float mean = s * invD;
    const float var  = s2 * invD - mean * mean;
    const float inv  = rsqrtf(var + 1e-5f);
    for (int i = 0; i < per; i++) {
        int j = i * 256 + t;
        float y = fmaxf(fmaf((v[i] - mean) * inv, g[j], be[j]), 0.0f);
        x[j] = (T)y;
    }
}

// ---------------------------------------------------------------------------
// Host side
// ---------------------------------------------------------------------------
template <typename OutT>
static void launch_gemm(int M, int N, int K,
                        const __half* A, int lda, const __half* Bt, int ldb,
                        OutT* C, int ldc, const float* bias,
                        OutT* C2 = nullptr, int ldc2 = 0, int nsplit = (1 << 30))
{
    dim3 grid(N / 128, M / 128);
    gemm_f16<OutT><<<grid, 256>>>(M, N, K, A, lda, Bt, ldb, C, ldc, bias, C2, ldc2, nsplit);
}

extern "C" void kernel_launch(void* const* d_in, const int* in_sizes, int n_in,
                              void* d_out, int out_size)
{
    const float* x   = (const float*)d_in[0];
    const float* W1  = (const float*)d_in[1];
    const float* b1  = (const float*)d_in[2];
    const float* g1  = (const float*)d_in[3];
    const float* be1 = (const float*)d_in[4];
    const float* W2  = (const float*)d_in[5];
    const float* b2  = (const float*)d_in[6];
    const float* g2  = (const float*)d_in[7];
    const float* be2 = (const float*)d_in[8];
    const float* WQ  = (const float*)d_in[9];
    const float* WK  = (const float*)d_in[10];
    const float* WV  = (const float*)d_in[11];
    const float* WO  = (const float*)d_in[12];
    const float* Wf  = (const float*)d_in[13];
    const float* bf  = (const float*)d_in[14];
    const float* gf  = (const float*)d_in[15];
    const float* bef = (const float*)d_in[16];
    float* out = (float*)d_out;

    cudaFuncSetAttribute(flash_kernel, cudaFuncAttributeMaxDynamicSharedMemorySize, FLASH_SMEM);

    __half *h, *tmp, *QKV, *AV, *cat, *W2t, *Wqkvt, *WOh, *Wcombt, *Wft;
    cudaGetSymbolAddress((void**)&h,      g_h);
    cudaGetSymbolAddress((void**)&tmp,    g_tmp);
    cudaGetSymbolAddress((void**)&QKV,    g_QKV);
    cudaGetSymbolAddress((void**)&AV,     g_AV);
    cudaGetSymbolAddress((void**)&cat,    g_cat);
    cudaGetSymbolAddress((void**)&W2t,    g_W2t);
    cudaGetSymbolAddress((void**)&Wqkvt,  g_Wqkvt);
    cudaGetSymbolAddress((void**)&WOh,    g_WOh);
    cudaGetSymbolAddress((void**)&Wcombt, g_Wcombt);
    cudaGetSymbolAddress((void**)&Wft,    g_Wft);

    // ---- weight prep ----
    tcvt_kernel<<<dim3(16, 16), 256>>>(W2, DMODEL, W2t, DMODEL);
    tcvt_kernel<<<dim3(16, 4),  256>>>(WQ, 128, Wqkvt, DMODEL);
    tcvt_kernel<<<dim3(16, 4),  256>>>(WK, 128, Wqkvt + 128 * DMODEL, DMODEL);
    tcvt_kernel<<<dim3(16, 16), 256>>>(WV, DMODEL, Wqkvt + 256 * DMODEL, DMODEL);
    tcvt_kernel<<<dim3(16, 16), 256>>>(WO, DMODEL, Wcombt, DMODEL);          // rows 0-511 = WO^T
    cvt_kernel<<<(DMODEL * DMODEL + 255) / 256, 256>>>(WO, WOh, DMODEL * DMODEL);
    tcvt_kernel<<<dim3(64, 32), 256>>>(Wf, OUTF, Wft, 4 * DMODEL);

    // Wcombt rows 512-1279 = (WO * Wqkv)^T: C[768,512] = Wqkvt @ WOh^T
    // C[m][n] = sum_k Wqkv[k][m] * WO[n][k]... (verified: equals (WO@Wqkv)^T)
    launch_gemm<__half>(768, DMODEL, DMODEL, Wqkvt, DMODEL, WOh, DMODEL,
                        Wcombt + 512 * DMODEL, DMODEL, nullptr);

    // ---- FF1 ----
    ff1_kernel<<<NROWS, 128>>>(x, W1, b1, g1, be1, h);

    // ---- FF2 ----
    launch_gemm<__half>(NROWS, DMODEL, DMODEL, h, DMODEL, W2t, DMODEL, tmp, DMODEL, b2);
    ln_relu_kernel<__half><<<NROWS, 256>>>(tmp, DMODEL, g2, be2);

    // ---- first QKV projection ----
    launch_gemm<__half>(NROWS, 768, DMODEL, tmp, DMODEL, Wqkvt, DMODEL, QKV, 768, nullptr);

    for (int it = 0; it < 4; it++) {
        // flash attention (reads g_QKV, writes AV)
        flash_kernel<<<dim3(2, 64), 256, FLASH_SMEM>>>(QKV, AV);

        __half* a_out = cat + it * DMODEL;
        if (it < 3) {
            // combined: cols 0-511 -> cat slice, cols 512-1279 -> QKV for next iter
            launch_gemm<__half>(NROWS, 1280, DMODEL, AV, DMODEL, Wcombt, DMODEL,
                                a_out, 4 * DMODEL, nullptr, QKV, 768, 512);
        } else {
            launch_gemm<__half>(NROWS, DMODEL, DMODEL, AV, DMODEL, Wcombt, DMODEL,
                                a_out, 4 * DMODEL, nullptr);
        }
    }

    // ---- Final FF ----
    launch_gemm<float>(NROWS, OUTF, 4 * DMODEL, cat, 4 * DMODEL, Wft, 4 * DMODEL, out, OUTF, bf);
    ln_relu_kernel<float><<<NROWS, 256>>>(out, OUTF, gf, bef);
}

// round 15
// speedup vs baseline: 1.0788x; 1.0265x over previous
#include <cuda_runtime.h>
#include <cuda_fp16.h>
#include <math.h>
#include <float.h>
#include <stdint.h>

// ---------------------------------------------------------------------------
// PointEncoder: FF1 -> FF2 -> 4x attention -> concat -> FF_final
// N=8192, D=512, MD=128, OUT_F=1024.
// FP16 tensor cores (fp32 accumulate), ldmatrix fragment loads.
// No-max softmax. Flash = R10 shape (best known; at crossbar floor).
// Critical path per iter = flash -> AV @ (WO*Wqkv). The AV@WO->cat GEMM
// runs on a SIDE STREAM shadowed under the next flash (20 idle SMs).
// ---------------------------------------------------------------------------

#define NROWS 8192
#define DMODEL 512
#define OUTF 1024

// Activations (fp16)
__device__ __half g_h[NROWS * DMODEL];
__device__ __half g_tmp[NROWS * DMODEL];
__device__ __half g_QKV[NROWS * 768];            // Q(128)|K(128)|V(512) per row
__device__ __half g_AV0[NROWS * DMODEL];
__device__ __half g_AV1[NROWS * DMODEL];
__device__ __half g_cat[NROWS * 4 * DMODEL];
// Weights (fp16)
__device__ __half g_W2t[DMODEL * DMODEL];        // [N][K]
__device__ __half g_Wqkvt[768 * DMODEL];         // [N][K]
__device__ __half g_WOh[DMODEL * DMODEL];        // WO plain convert
__device__ __half g_WOt[DMODEL * DMODEL];        // WO^T
__device__ __half g_WOqkvt[768 * DMODEL];        // (WO @ Wqkv)^T
__device__ __half g_Wft[OUTF * 4 * DMODEL];

__device__ __forceinline__ uint32_t pack2(float x, float y) {
    __half2 h = __floats2half2_rn(x, y);
    return *(uint32_t*)&h;
}

// ---------------------------------------------------------------------------
// Reductions
// ---------------------------------------------------------------------------
__device__ __forceinline__ float warpReduceSum(float v) {
#pragma unroll
    for (int o = 16; o > 0; o >>= 1) v += __shfl_xor_sync(0xffffffff, v, o);
    return v;
}
__device__ float blockReduceSum(float v) {
    __shared__ float sh[32];
    __shared__ float res;
    int lane = threadIdx.x & 31, wid = threadIdx.x >> 5;
    v = warpReduceSum(v);
    if (lane == 0) sh[wid] = v;
    __syncthreads();
    int nw = (blockDim.x + 31) >> 5;
    float t = (threadIdx.x < nw) ? sh[threadIdx.x] : 0.0f;
    if (wid == 0) { t = warpReduceSum(t); if (lane == 0) res = t; }
    __syncthreads();
    return res;
}

// ---------------------------------------------------------------------------
// cp.async + ldmatrix helpers
// ---------------------------------------------------------------------------
__device__ __forceinline__ void cp16h(__half* dst, const __half* src) {
    uint32_t d = (uint32_t)__cvta_generic_to_shared(dst);
    asm volatile("cp.async.cg.shared.global [%0], [%1], 16;\n" :: "r"(d), "l"(src));
}
__device__ __forceinline__ void cp_commit() { asm volatile("cp.async.commit_group;\n"); }
__device__ __forceinline__ void cp_wait1() { asm volatile("cp.async.wait_group 1;\n"); }
__device__ __forceinline__ void cp_wait0() { asm volatile("cp.async.wait_group 0;\n"); }

__device__ __forceinline__ void ldsm4(uint32_t& r0, uint32_t& r1, uint32_t& r2, uint32_t& r3,
                                      uint32_t addr) {
    asm volatile("ldmatrix.sync.aligned.m8n8.x4.shared.b16 {%0,%1,%2,%3}, [%4];"
                 : "=r"(r0), "=r"(r1), "=r"(r2), "=r"(r3) : "r"(addr));
}
__device__ __forceinline__ void ldsm4t(uint32_t& r0, uint32_t& r1, uint32_t& r2, uint32_t& r3,
                                       uint32_t addr) {
    asm volatile("ldmatrix.sync.aligned.m8n8.x4.trans.shared.b16 {%0,%1,%2,%3}, [%4];"
                 : "=r"(r0), "=r"(r1), "=r"(r2), "=r"(r3) : "r"(addr));
}

#define MMA_F16(c, a0, a1, a2, a3, b0, b1)                                   \
    asm volatile(                                                            \
        "mma.sync.aligned.m16n8k16.row.col.f32.f16.f16.f32 "                 \
        "{%0,%1,%2,%3},{%4,%5,%6,%7},{%8,%9},{%0,%1,%2,%3};"                 \
        : "+f"((c)[0]), "+f"((c)[1]), "+f"((c)[2]), "+f"((c)[3])             \
        : "r"(a0), "r"(a1), "r"(a2), "r"(a3), "r"(b0), "r"(b1))

// ---------------------------------------------------------------------------
// FP16 GEMM (NT): C[M,N] = A[M,K] @ Bt[N,K]^T + bias   (R10 version)
// ---------------------------------------------------------------------------
#define HST 40
#define HSZ (128 * HST)

template <typename OutT>
__global__ void __launch_bounds__(256, 2) gemm_f16(
    int M, int N, int K,
    const __half* __restrict__ A, int lda,
    const __half* __restrict__ Bt, int ldb,
    OutT* __restrict__ C, int ldc,
    const float* __restrict__ bias)
{
    __shared__ __half sm[4 * HSZ];

    const int t    = threadIdx.x;
    const int wid  = t >> 5;
    const int lane = t & 31;
    const int g    = lane >> 2;
    const int t4   = lane & 3;
    const int wm   = wid & 1;
    const int wn   = wid >> 1;
    const int bx   = blockIdx.x;
    const int by   = blockIdx.y;

    const int arow = lane & 15;
    const int acol = (lane >> 4) << 3;
    const int brow = ((lane >> 4) << 3) | (lane & 7);
    const int bcol = ((lane >> 3) & 1) << 3;

    const uint32_t smb = (uint32_t)__cvta_generic_to_shared(sm);

    const __half* Ab = A  + (size_t)by * 128 * lda;
    const __half* Bb = Bt + (size_t)bx * 128 * ldb;

    const int lr = t >> 1;
    const int lc = (t & 1) * 16;

    float acc[4][4][4];
#pragma unroll
    for (int mt = 0; mt < 4; mt++)
#pragma unroll
        for (int nt = 0; nt < 4; nt++)
#pragma unroll
            for (int r = 0; r < 4; r++) acc[mt][nt][r] = 0.0f;

    const int tiles = K / 32;

    auto load_tile = [&](int stage, int k0) {
        __half* as = sm + stage * HSZ;
        __half* bs = sm + (2 + stage) * HSZ;
        cp16h(as + lr * HST + lc,     Ab + (size_t)lr * lda + k0 + lc);
        cp16h(as + lr * HST + lc + 8, Ab + (size_t)lr * lda + k0 + lc + 8);
        cp16h(bs + lr * HST + lc,     Bb + (size_t)lr * ldb + k0 + lc);
        cp16h(bs + lr * HST + lc + 8, Bb + (size_t)lr * ldb + k0 + lc + 8);
        cp_commit();
    };

    load_tile(0, 0);

    for (int tt = 0; tt < tiles; tt++) {
        if (tt + 1 < tiles) {
            load_tile((tt + 1) & 1, (tt + 1) * 32);
            cp_wait1();
        } else {
            cp_wait0();
        }
        __syncthreads();

        const int stage = tt & 1;
        const uint32_t abase = smb + (stage * HSZ) * 2;
        const uint32_t bbase = smb + ((2 + stage) * HSZ) * 2;

#pragma unroll
        for (int ks = 0; ks < 2; ks++) {
            uint32_t a[4][4];
#pragma unroll
            for (int mt = 0; mt < 4; mt++) {
                uint32_t ad = abase + (((wm * 64 + mt * 16 + arow) * HST) + ks * 16 + acol) * 2;
                ldsm4(a[mt][0], a[mt][1], a[mt][2], a[mt][3], ad);
            }
            uint32_t b[4][2];
#pragma unroll
            for (int np = 0; np < 2; np++) {
                uint32_t bd = bbase + (((wn * 32 + np * 16 + brow) * HST) + ks * 16 + bcol) * 2;
                ldsm4(b[2 * np][0], b[2 * np][1], b[2 * np + 1][0], b[2 * np + 1][1], bd);
            }
#pragma unroll
            for (int mt = 0; mt < 4; mt++)
#pragma unroll
                for (int nt = 0; nt < 4; nt++)
                    MMA_F16(acc[mt][nt], a[mt][0], a[mt][1], a[mt][2], a[mt][3],
                            b[nt][0], b[nt][1]);
        }
        __syncthreads();
    }

#pragma unroll
    for (int mt = 0; mt < 4; mt++) {
        const int gr = by * 128 + wm * 64 + mt * 16 + g;
#pragma unroll
        for (int nt = 0; nt < 4; nt++) {
            const int gc = bx * 128 + wn * 32 + nt * 8 + 2 * t4;
            float b0 = bias ? bias[gc] : 0.0f;
            float b1 = bias ? bias[gc + 1] : 0.0f;
            float v0 = acc[mt][nt][0] + b0;
            float v1 = acc[mt][nt][1] + b1;
            float v2 = acc[mt][nt][2] + b0;
            float v3 = acc[mt][nt][3] + b1;
            if (sizeof(OutT) == 2) {
                *(uint32_t*)((__half*)C + (size_t)gr * ldc + gc)       = pack2(v0, v1);
                *(uint32_t*)((__half*)C + (size_t)(gr + 8) * ldc + gc) = pack2(v2, v3);
            } else {
                *(float2*)((float*)C + (size_t)gr * ldc + gc)       = make_float2(v0, v1);
                *(float2*)((float*)C + (size_t)(gr + 8) * ldc + gc) = make_float2(v2, v3);
            }
        }
    }
}

// ---------------------------------------------------------------------------
// Fused flash attention (fp16), no-max softmax (R10 structure, unchanged)
// ---------------------------------------------------------------------------
#define FKT 64
#define FNT (NROWS / FKT)
#define KST 136
#define VST 264
#define QSTG 136
#define SMK_SZ (FKT * KST)
#define SMV_SZ (FKT * VST)
#define FLASH_SMEM ((2 * SMK_SZ + 2 * SMV_SZ) * 2)   // 102400 bytes

__global__ void __launch_bounds__(256, 1) flash_kernel(
    const __half* __restrict__ QKV, __half* __restrict__ O)
{
    extern __shared__ __half smh[];
    __half* smK = smh;
    __half* smV = smh + 2 * SMK_SZ;

    const int t    = threadIdx.x;
    const int w    = t >> 5;
    const int lane = t & 31;
    const int g    = lane >> 2;
    const int t4   = lane & 3;
    const int vh   = blockIdx.x;
    const int qb   = blockIdx.y;

    const int arow = lane & 15;
    const int acol = (lane >> 4) << 3;
    const int brow = ((lane >> 4) << 3) | (lane & 7);
    const int bcol = ((lane >> 3) & 1) << 3;
    const int vkey = bcol | (lane & 7);
    const int vcg  = (lane >> 4) << 3;

    const uint32_t smb    = (uint32_t)__cvta_generic_to_shared(smh);
    const uint32_t kbase0 = smb;
    const uint32_t vbase0 = smb + (2 * SMK_SZ) * 2;

    const __half* Vg = QKV + 256 + vh * 256;

#pragma unroll
    for (int i = 0; i < 8; i++) {
        int idx = t + i * 256;
        int r = idx >> 4, c = (idx & 15) * 8;
        cp16h(smV + r * QSTG + c, QKV + (size_t)(qb * 128 + r) * 768 + c);
    }
    cp_commit();
    cp_wait0();
    __syncthreads();

    uint32_t qa[8][4];
#pragma unroll
    for (int ks = 0; ks < 8; ks++) {
        uint32_t ad = vbase0 + (((w * 16 + arow) * QSTG) + ks * 16 + acol) * 2;
        ldsm4(qa[ks][0], qa[ks][1], qa[ks][2], qa[ks][3], ad);
    }
    __syncthreads();

    {
#pragma unroll
        for (int i = 0; i < 4; i++) {
            int idx = t + i * 256;
            int r = idx >> 4, c = (idx & 15) * 8;
            cp16h(smK + r * KST + c, QKV + (size_t)r * 768 + 128 + c);
        }
#pragma unroll
        for (int i = 0; i < 8; i++) {
            int idx = t + i * 256;
            int r = idx >> 5, c = (idx & 31) * 8;
            cp16h(smV + r * VST + c, Vg + (size_t)r * 768 + c);
        }
        cp_commit();
    }

    const float c_exp = 0.12753102150208952f;   // (1/sqrt(128)) * log2(e)

    float l0 = 0.0f, l1 = 0.0f;
    float o[32][4];
#pragma unroll
    for (int nt = 0; nt < 32; nt++)
#pragma unroll
        for (int r = 0; r < 4; r++) o[nt][r] = 0.0f;

    for (int kt = 0; kt < FNT; kt++) {
        cp_wait0();
        __syncthreads();

        if (kt + 1 < FNT) {
            const int st = (kt + 1) & 1;
            __half* kd = smK + st * SMK_SZ;
            __half* vd = smV + st * SMV_SZ;
#pragma unroll
            for (int i = 0; i < 4; i++) {
                int idx = t + i * 256;
                int r = idx >> 4, c = (idx & 15) * 8;
                cp16h(kd + r * KST + c,
                      QKV + (size_t)((kt + 1) * FKT + r) * 768 + 128 + c);
            }
#pragma unroll
            for (int i = 0; i < 8; i++) {
                int idx = t + i * 256;
                int r = idx >> 5, c = (idx & 31) * 8;
                cp16h(vd + r * VST + c, Vg + (size_t)((kt + 1) * FKT + r) * 768 + c);
            }
            cp_commit();
        }

        float s[8][4];
#pragma unroll
        for (int nt = 0; nt < 8; nt++)
#pragma unroll
            for (int r = 0; r < 4; r++) s[nt][r] = 0.0f;

        const uint32_t kb = kbase0 + ((kt & 1) * SMK_SZ) * 2;
#pragma unroll
        for (int ks = 0; ks < 8; ks++) {
#pragma unroll
            for (int np = 0; np < 4; np++) {
                uint32_t b0e, b1e, b0o, b1o;
                uint32_t bd = kb + (((np * 16 + brow) * KST) + ks * 16 + bcol) * 2;
                ldsm4(b0e, b1e, b0o, b1o, bd);
                MMA_F16(s[2 * np],     qa[ks][0], qa[ks][1], qa[ks][2], qa[ks][3], b0e, b1e);
                MMA_F16(s[2 * np + 1], qa[ks][0], qa[ks][1], qa[ks][2], qa[ks][3], b0o, b1o);
            }
        }

        uint32_t pa[4][4];
#pragma unroll
        for (int j = 0; j < 4; j++) {
            float e00 = exp2f(s[2 * j][0] * c_exp);
            float e01 = exp2f(s[2 * j][1] * c_exp);
            float e02 = exp2f(s[2 * j][2] * c_exp);
            float e03 = exp2f(s[2 * j][3] * c_exp);
            float e10 = exp2f(s[2 * j + 1][0] * c_exp);
            float e11 = exp2f(s[2 * j + 1][1] * c_exp);
            float e12 = exp2f(s[2 * j + 1][2] * c_exp);
            float e13 = exp2f(s[2 * j + 1][3] * c_exp);
            l0 += e00 + e01 + e10 + e11;
            l1 += e02 + e03 + e12 + e13;
            pa[j][0] = pack2(e00, e01);
            pa[j][1] = pack2(e02, e03);
            pa[j][2] = pack2(e10, e11);
            pa[j][3] = pack2(e12, e13);
        }

        const uint32_t vb = vbase0 + ((kt & 1) * SMV_SZ) * 2;
#pragma unroll
        for (int j = 0; j < 4; j++) {
#pragma unroll
            for (int np = 0; np < 16; np++) {
                uint32_t b0e, b1e, b0o, b1o;
                uint32_t vd = vb + (((j * 16 + vkey) * VST) + np * 16 + vcg) * 2;
                ldsm4t(b0e, b1e, b0o, b1o, vd);
                MMA_F16(o[2 * np],     pa[j][0], pa[j][1], pa[j][2], pa[j][3], b0e, b1e);
                MMA_F16(o[2 * np + 1], pa[j][0], pa[j][1], pa[j][2], pa[j][3], b0o, b1o);
            }
        }
    }

    l0 += __shfl_xor_sync(0xffffffff, l0, 1);
    l0 += __shfl_xor_sync(0xffffffff, l0, 2);
    l1 += __shfl_xor_sync(0xffffffff, l1, 1);
    l1 += __shfl_xor_sync(0xffffffff, l1, 2);
    const float il0 = 1.0f / l0;
    const float il1 = 1.0f / l1;
    const int r0 = qb * 128 + w * 16 + g;
    const int colb = vh * 256 + 2 * t4;
#pragma unroll
    for (int nt = 0; nt < 32; nt++) {
        int gc = colb + nt * 8;
        *(uint32_t*)(O + (size_t)r0 * DMODEL + gc) =
            pack2(o[nt][0] * il0, o[nt][1] * il0);
        *(uint32_t*)(O + (size_t)(r0 + 8) * DMODEL + gc) =
            pack2(o[nt][2] * il1, o[nt][3] * il1);
    }
}

// ---------------------------------------------------------------------------
// Weight prep kernels
// ---------------------------------------------------------------------------
__global__ void tcvt_kernel(const float* __restrict__ in, int ldin,
                            __half* __restrict__ out, int ldout)
{
    __shared__ float sm[32][33];
    const int k0 = blockIdx.x * 32;
    const int n0 = blockIdx.y * 32;
    const int tx = threadIdx.x & 31;
    const int ty = threadIdx.x >> 5;
#pragma unroll
    for (int i = 0; i < 4; i++)
        sm[ty + 8 * i][tx] = in[(size_t)(k0 + ty + 8 * i) * ldin + n0 + tx];
    __syncthreads();
#pragma unroll
    for (int i = 0; i < 4; i++)
        out[(size_t)(n0 + ty + 8 * i) * ldout + k0 + tx] =
            __float2half_rn(sm[tx][ty + 8 * i]);
}

__global__ void cvt_kernel(const float* __restrict__ in, __half* __restrict__ out, int n)
{
    int i = blockIdx.x * blockDim.x + threadIdx.x;
    if (i < n) out[i] = __float2half_rn(in[i]);
}

// ---------------------------------------------------------------------------
// FF1: h = fp16(relu(LN(x @ W1 + b1)))
// ---------------------------------------------------------------------------
__global__ void __launch_bounds__(128) ff1_kernel(
    const float* __restrict__ x, const float* __restrict__ W1,
    const float* __restrict__ b1, const float* __restrict__ g1,
    const float* __restrict__ be1, __half* __restrict__ out)
{
    const int row = blockIdx.x;
    const float x0 = x[row * 3 + 0];
    const float x1 = x[row * 3 + 1];
    const float x2 = x[row * 3 + 2];
    const int t = threadIdx.x;

    float v[4];
    float s = 0.0f, s2 = 0.0f;
#pragma unroll
    for (int i = 0; i < 4; i++) {
        int j = i * 128 + t;
        float val = fmaf(x0, W1[j], fmaf(x1, W1[DMODEL + j], fmaf(x2, W1[2 * DMODEL + j], b1[j])));
        v[i] = val;
        s += val;
        s2 = fmaf(val, val, s2);
    }
    s  = blockReduceSum(s);
    s2 = blockReduceSum(s2);
    const float mean = s * (1.0f / DMODEL);
    const float var  = s2 * (1.0f / DMODEL) - mean * mean;
    const float inv  = rsqrtf(var + 1e-5f);
#pragma unroll
    for (int i = 0; i < 4; i++) {
        int j = i * 128 + t;
        float y = fmaf((v[i] - mean) * inv, g1[j], be1[j]);
        out[(size_t)row * DMODEL + j] = __float2half_rn(fmaxf(y, 0.0f));
    }
}

// ---------------------------------------------------------------------------
// LayerNorm + ReLU, in-place
// ---------------------------------------------------------------------------
template <typename T>
__global__ void __launch_bounds__(256) ln_relu_kernel(
    T* __restrict__ X, int D, const float* __restrict__ g, const float* __restrict__ be)
{
    const int row = blockIdx.x;
    T* x = X + (size_t)row * D;
    const int t = threadIdx.x;
    const int per = D >> 8;

    float v[4];
    float s = 0.0f, s2 = 0.0f;
    for (int i = 0; i < per; i++) {
        float val = (float)x[i * 256 + t];
        v[i] = val;
        s += val;
        s2 = fmaf(val, val, s2);
    }
    s  = blockReduceSum(s);
    s2 = blockReduceSum(s2);
    const float invD = 1.0f / (float)D;
    const float mean = s * invD;
    const float var  = s2 * invD - mean * mean;
    const float inv  = rsqrtf(var + 1e-5f);
    for (int i = 0; i < per; i++) {
        int j = i * 256 + t;
        float y = fmaxf(fmaf((v[i] - mean) * inv, g[j], be[j]), 0.0f);
        x[j] = (T)y;
    }
}

// ---------------------------------------------------------------------------
// Host side
// ---------------------------------------------------------------------------
template <typename OutT>
static void launch_gemm(int M, int N, int K,
                        const __half* A, int lda, const __half* Bt, int ldb,
                        OutT* C, int ldc, const float* bias, cudaStream_t st = 0)
{
    dim3 grid(N / 128, M / 128);
    gemm_f16<OutT><<<grid, 256, 0, st>>>(M, N, K, A, lda, Bt, ldb, C, ldc, bias);
}

// Created once on the first (correctness) call; reused during graph capture.
static cudaStream_t s_side = nullptr;
static cudaEvent_t  s_ev_fork = nullptr, s_ev_prep = nullptr;
static cudaEvent_t  s_ev_f[4], s_ev_c[4];

extern "C" void kernel_launch(void* const* d_in, const int* in_sizes, int n_in,
                              void* d_out, int out_size)
{
    const float* x   = (const float*)d_in[0];
    const float* W1  = (const float*)d_in[1];
    const float* b1  = (const float*)d_in[2];
    const float* g1  = (const float*)d_in[3];
    const float* be1 = (const float*)d_in[4];
    const float* W2  = (const float*)d_in[5];
    const float* b2  = (const float*)d_in[6];
    const float* g2  = (const float*)d_in[7];
    const float* be2 = (const float*)d_in[8];
    const float* WQ  = (const float*)d_in[9];
    const float* WK  = (const float*)d_in[10];
    const float* WV  = (const float*)d_in[11];
    const float* WO  = (const float*)d_in[12];
    const float* Wf  = (const float*)d_in[13];
    const float* bf  = (const float*)d_in[14];
    const float* gf  = (const float*)d_in[15];
    const float* bef = (const float*)d_in[16];
    float* out = (float*)d_out;

    if (!s_side) {
        cudaStreamCreateWithFlags(&s_side, cudaStreamNonBlocking);
        cudaEventCreateWithFlags(&s_ev_fork, cudaEventDisableTiming);
        cudaEventCreateWithFlags(&s_ev_prep, cudaEventDisableTiming);
        for (int i = 0; i < 4; i++) {
            cudaEventCreateWithFlags(&s_ev_f[i], cudaEventDisableTiming);
            cudaEventCreateWithFlags(&s_ev_c[i], cudaEventDisableTiming);
        }
    }

    cudaFuncSetAttribute(flash_kernel, cudaFuncAttributeMaxDynamicSharedMemorySize, FLASH_SMEM);

    __half *h, *tmp, *QKV, *AV0, *AV1, *cat, *W2t, *Wqkvt, *WOh, *WOt, *WOqkvt, *Wft;
    cudaGetSymbolAddress((void**)&h,      g_h);
    cudaGetSymbolAddress((void**)&tmp,    g_tmp);
    cudaGetSymbolAddress((void**)&QKV,    g_QKV);
    cudaGetSymbolAddress((void**)&AV0,    g_AV0);
    cudaGetSymbolAddress((void**)&AV1,    g_AV1);
    cudaGetSymbolAddress((void**)&cat,    g_cat);
    cudaGetSymbolAddress((void**)&W2t,    g_W2t);
    cudaGetSymbolAddress((void**)&Wqkvt,  g_Wqkvt);
    cudaGetSymbolAddress((void**)&WOh,    g_WOh);
    cudaGetSymbolAddress((void**)&WOt,    g_WOt);
    cudaGetSymbolAddress((void**)&WOqkvt, g_WOqkvt);
    cudaGetSymbolAddress((void**)&Wft,    g_Wft);

    // ---- fork side stream for weight prep ----
    cudaEventRecord(s_ev_fork, 0);
    cudaStreamWaitEvent(s_side, s_ev_fork, 0);

    // side: everything needed from the first QKV projection onward
    tcvt_kernel<<<dim3(16, 4),  256, 0, s_side>>>(WQ, 128, Wqkvt, DMODEL);
    tcvt_kernel<<<dim3(16, 4),  256, 0, s_side>>>(WK, 128, Wqkvt + 128 * DMODEL, DMODEL);
    tcvt_kernel<<<dim3(16, 16), 256, 0, s_side>>>(WV, DMODEL, Wqkvt + 256 * DMODEL, DMODEL);
    tcvt_kernel<<<dim3(16, 16), 256, 0, s_side>>>(WO, DMODEL, WOt, DMODEL);
    cvt_kernel<<<(DMODEL * DMODEL + 255) / 256, 256, 0, s_side>>>(WO, WOh, DMODEL * DMODEL);
    tcvt_kernel<<<dim3(64, 32), 256, 0, s_side>>>(Wf, OUTF, Wft, 4 * DMODEL);
    // WOqkvt[768][512] = (WO @ Wqkv)^T
    launch_gemm<__half>(768, DMODEL, DMODEL, Wqkvt, DMODEL, WOh, DMODEL,
                        WOqkvt, DMODEL, nullptr, s_side);
    cudaEventRecord(s_ev_prep, s_side);

    // main: FF1 -> FF2 (needs only W2t, prepared on main)
    tcvt_kernel<<<dim3(16, 16), 256>>>(W2, DMODEL, W2t, DMODEL);
    ff1_kernel<<<NROWS, 128>>>(x, W1, b1, g1, be1, h);
    launch_gemm<__half>(NROWS, DMODEL, DMODEL, h, DMODEL, W2t, DMODEL, tmp, DMODEL, b2);
    ln_relu_kernel<__half><<<NROWS, 256>>>(tmp, DMODEL, g2, be2);

    // main waits for Wqkvt, then first QKV projection
    cudaStreamWaitEvent(0, s_ev_prep, 0);
    launch_gemm<__half>(NROWS, 768, DMODEL, tmp, DMODEL, Wqkvt, DMODEL, QKV, 768, nullptr);

    for (int it = 0; it < 4; it++) {
        __half* AVb = (it & 1) ? AV1 : AV0;

        // AVb was last read by the side cat-GEMM of iteration it-2 -> wait it
        if (it >= 2) cudaStreamWaitEvent(0, s_ev_c[it - 2], 0);

        // flash attention (reads QKV, writes AVb)
        flash_kernel<<<dim3(2, 64), 256, FLASH_SMEM>>>(QKV, AVb);
        cudaEventRecord(s_ev_f[it], 0);

        // critical path: QKV for next iteration directly from AVb
        if (it < 3)
            launch_gemm<__half>(NROWS, 768, DMODEL, AVb, DMODEL, WOqkvt, DMODEL,
                                QKV, 768, nullptr);

        // shadowed: cat slice = AVb @ WO on side stream
        cudaStreamWaitEvent(s_side, s_ev_f[it], 0);
        launch_gemm<__half>(NROWS, DMODEL, DMODEL, AVb, DMODEL, WOt, DMODEL,
                            cat + it * DMODEL, 4 * DMODEL, nullptr, s_side);
        cudaEventRecord(s_ev_c[it], s_side);
    }

    // join: final FF needs all cat slices
    cudaStreamWaitEvent(0, s_ev_c[2], 0);
    cudaStreamWaitEvent(0, s_ev_c[3], 0);
    launch_gemm<float>(NROWS, OUTF, 4 * DMODEL, cat, 4 * DMODEL, Wft, 4 * DMODEL, out, OUTF, bf);
    ln_relu_kernel<float><<<NROWS, 256>>>(out, OUTF, gf, bef);
}